// round 1
// baseline (speedup 1.0000x reference)
#include <cuda_runtime.h>
#include <math.h>

#define BB 4
#define SS 1024
#define EE 768
#define HH 12
#define DD 64
#define MT (BB*SS)
#define SCALING 0.125f

// Scratch (device globals: allocation-free rule)
__device__ float g_Q[BB*HH*SS*DD];
__device__ float g_K[BB*HH*SS*DD];
__device__ float g_V[BB*HH*SS*DD];
__device__ float g_AO[BB*SS*EE];

// exp(x) for x <= 0, FMA-pipe only (avoids MUFU bottleneck).
// 2^t with t = x*log2(e); degree-7 poly for 2^frac, bit-trick for 2^int.
// Max rel error ~1.3e-6.
__device__ __forceinline__ float fexp(float x) {
    float t = x * 1.4426950408889634f;
    t = fmaxf(t, -125.0f);
    float fi = floorf(t);
    float f = t - fi;
    float p = 1.525273380e-5f;
    p = fmaf(p, f, 1.540353039e-4f);
    p = fmaf(p, f, 1.333355815e-3f);
    p = fmaf(p, f, 9.618129108e-3f);
    p = fmaf(p, f, 5.550410866e-2f);
    p = fmaf(p, f, 2.402265070e-1f);
    p = fmaf(p, f, 6.931471806e-1f);
    p = fmaf(p, f, 1.0f);
    int e = (int)fi;
    float s = __int_as_float((e + 127) << 23);
    return p * s;
}

// ---------------------------------------------------------------------------
// QKV projection: C = X(M,K) @ W(N,K)^T + b.  BM=BN=64, BK=16, 256 thr, 4x4.
// Output written directly in [B,H,S,D] layout. blockIdx.z selects q/k/v.
// ---------------------------------------------------------------------------
__global__ void __launch_bounds__(256) qkv_kernel(
    const float* __restrict__ X,
    const float* __restrict__ Wq, const float* __restrict__ bq,
    const float* __restrict__ Wk, const float* __restrict__ bk,
    const float* __restrict__ Wv, const float* __restrict__ bv)
{
    const int which = blockIdx.z;
    const float* Wm = (which == 0) ? Wq : (which == 1) ? Wk : Wv;
    const float* bb = (which == 0) ? bq : (which == 1) ? bk : bv;
    float* out = (which == 0) ? g_Q : (which == 1) ? g_K : g_V;
    const float scale = (which == 0) ? SCALING : 1.0f;

    const int n0 = blockIdx.x * 64;
    const int m0 = blockIdx.y * 64;

    __shared__ float As[16][64];   // [k][m]
    __shared__ float Bs[16][64];   // [k][n]

    const int tid = threadIdx.x;
    const int tx = tid & 15, ty = tid >> 4;
    const int lrow = tid >> 2;          // 0..63
    const int lk4 = (tid & 3) << 2;     // 0,4,8,12

    float acc[4][4] = {};

    for (int k0 = 0; k0 < EE; k0 += 16) {
        float4 a = *(const float4*)(X  + (size_t)(m0 + lrow) * EE + k0 + lk4);
        float4 w = *(const float4*)(Wm + (size_t)(n0 + lrow) * EE + k0 + lk4);
        As[lk4+0][lrow]=a.x; As[lk4+1][lrow]=a.y; As[lk4+2][lrow]=a.z; As[lk4+3][lrow]=a.w;
        Bs[lk4+0][lrow]=w.x; Bs[lk4+1][lrow]=w.y; Bs[lk4+2][lrow]=w.z; Bs[lk4+3][lrow]=w.w;
        __syncthreads();
        #pragma unroll
        for (int kk = 0; kk < 16; kk++) {
            float4 av  = *(const float4*)&As[kk][ty*4];
            float4 bv4 = *(const float4*)&Bs[kk][tx*4];
            float ar[4]={av.x,av.y,av.z,av.w};
            float br[4]={bv4.x,bv4.y,bv4.z,bv4.w};
            #pragma unroll
            for (int i=0;i<4;i++)
                #pragma unroll
                for (int j=0;j<4;j++)
                    acc[i][j] = fmaf(ar[i], br[j], acc[i][j]);
        }
        __syncthreads();
    }

    const int h  = n0 >> 6;       // n0 is a multiple of 64
    const int d0 = tx * 4;
    float4 bv4 = *(const float4*)(bb + n0 + d0);
    float bias4[4] = {bv4.x, bv4.y, bv4.z, bv4.w};
    #pragma unroll
    for (int i = 0; i < 4; i++) {
        int m = m0 + ty*4 + i;
        int b = m >> 10, s = m & 1023;
        float4 o;
        o.x = (acc[i][0] + bias4[0]) * scale;
        o.y = (acc[i][1] + bias4[1]) * scale;
        o.z = (acc[i][2] + bias4[2]) * scale;
        o.w = (acc[i][3] + bias4[3]) * scale;
        *(float4*)(out + ((size_t)((b*HH + h)*SS + s))*DD + d0) = o;
    }
}

// ---------------------------------------------------------------------------
// Flash attention with relative-position bias. One CTA = (b, h, 64-row Qtile).
// Smem: Qs[d][q] 16KB, KP 16KB (K as [d][k], then reused for P as [k][q]
// with 4-float rotate swizzle), Vs[k][d] 16KB. 256 threads, 4x4 microtiles.
// ---------------------------------------------------------------------------
__global__ void __launch_bounds__(256) attn_kernel(
    const int* __restrict__ pos_row, const int* __restrict__ pos_col,
    const float* __restrict__ rel_table)
{
    const int qt = blockIdx.x;
    const int h  = blockIdx.y;
    const int b  = blockIdx.z;
    const int q0 = qt * 64;
    const float* Qp = g_Q + (size_t)(b*HH + h) * SS * DD;
    const float* Kp = g_K + (size_t)(b*HH + h) * SS * DD;
    const float* Vp = g_V + (size_t)(b*HH + h) * SS * DD;

    __shared__ float Qs[64*64];
    __shared__ float KP[64*64];
    __shared__ float Vs[64*64];

    const int tid = threadIdx.x;
    const int tx = tid & 15, ty = tid >> 4;
    const int lrow = tid >> 2;          // 0..63
    const int lc4 = (tid & 3) << 2;     // 0,4,8,12

    // Q tile -> Qs transposed [d][q]
    #pragma unroll
    for (int it = 0; it < 4; it++) {
        int dd = lc4 + it*16;
        float4 v = *(const float4*)(Qp + (size_t)(q0 + lrow)*DD + dd);
        Qs[(dd+0)*64 + lrow] = v.x;
        Qs[(dd+1)*64 + lrow] = v.y;
        Qs[(dd+2)*64 + lrow] = v.z;
        Qs[(dd+3)*64 + lrow] = v.w;
    }

    int rqr[4], rqc[4];
    #pragma unroll
    for (int i = 0; i < 4; i++) {
        int q = q0 + ty*4 + i;
        rqr[i] = pos_row[b*SS + q];
        rqc[i] = pos_col[b*SS + q];
    }
    const float tb0 = rel_table[0*HH + h];
    const float tb1 = rel_table[1*HH + h];
    const float tb2 = rel_table[2*HH + h];
    const float tb3 = rel_table[3*HH + h];

    float m_i[4], l_i[4], Oacc[4][4];
    #pragma unroll
    for (int i = 0; i < 4; i++) {
        m_i[i] = -1e30f; l_i[i] = 0.f;
        #pragma unroll
        for (int j = 0; j < 4; j++) Oacc[i][j] = 0.f;
    }

    for (int kt = 0; kt < SS/64; kt++) {
        const int kb = kt * 64;
        __syncthreads();   // previous iteration's reads of KP/Vs complete

        // K tile -> KP transposed [d][k]; V tile -> Vs [k][d]
        #pragma unroll
        for (int it = 0; it < 4; it++) {
            int dd = lc4 + it*16;
            float4 v = *(const float4*)(Kp + (size_t)(kb + lrow)*DD + dd);
            KP[(dd+0)*64 + lrow] = v.x;
            KP[(dd+1)*64 + lrow] = v.y;
            KP[(dd+2)*64 + lrow] = v.z;
            KP[(dd+3)*64 + lrow] = v.w;
            float4 vv = *(const float4*)(Vp + (size_t)(kb + lrow)*DD + dd);
            *(float4*)&Vs[lrow*64 + dd] = vv;
        }
        __syncthreads();

        // S = Q K^T (64x64 tile)
        float acc[4][4] = {};
        #pragma unroll
        for (int d = 0; d < 64; d++) {
            float4 av = *(const float4*)&Qs[d*64 + ty*4];
            float4 bv = *(const float4*)&KP[d*64 + tx*4];
            float ar[4]={av.x,av.y,av.z,av.w}, br[4]={bv.x,bv.y,bv.z,bv.w};
            #pragma unroll
            for (int i=0;i<4;i++)
                #pragma unroll
                for (int j=0;j<4;j++)
                    acc[i][j] = fmaf(ar[i], br[j], acc[i][j]);
        }

        // relative-position bias
        int rkr[4], rkc[4];
        #pragma unroll
        for (int j = 0; j < 4; j++) {
            int k = kb + tx*4 + j;
            rkr[j] = pos_row[b*SS + k];
            rkc[j] = pos_col[b*SS + k];
        }
        #pragma unroll
        for (int i = 0; i < 4; i++)
            #pragma unroll
            for (int j = 0; j < 4; j++) {
                bool r0 = (rqr[i] == rkr[j]);
                bool c0 = (rqc[i] == rkc[j]);
                float bias = r0 ? (c0 ? tb3 : tb1) : (c0 ? tb2 : tb0);
                acc[i][j] += bias;
            }

        // online softmax (row groups = 16 lanes sharing ty)
        #pragma unroll
        for (int i = 0; i < 4; i++) {
            float mx = fmaxf(fmaxf(acc[i][0], acc[i][1]), fmaxf(acc[i][2], acc[i][3]));
            #pragma unroll
            for (int off = 8; off > 0; off >>= 1)
                mx = fmaxf(mx, __shfl_xor_sync(0xffffffffu, mx, off));
            float mnew = fmaxf(m_i[i], mx);
            float sc = fexp(m_i[i] - mnew);
            m_i[i] = mnew;
            float rs = 0.f;
            #pragma unroll
            for (int j = 0; j < 4; j++) {
                acc[i][j] = fexp(acc[i][j] - mnew);
                rs += acc[i][j];
            }
            #pragma unroll
            for (int off = 8; off > 0; off >>= 1)
                rs += __shfl_xor_sync(0xffffffffu, rs, off);
            l_i[i] = l_i[i] * sc + rs;
            #pragma unroll
            for (int j = 0; j < 4; j++) Oacc[i][j] *= sc;
        }

        __syncthreads();   // done reading K from KP

        // P -> KP as [k][q] with rotate swizzle (conflict mitigation)
        #pragma unroll
        for (int j = 0; j < 4; j++) {
            int k = tx*4 + j;
            int qoff = (ty*4 + 4*k) & 63;
            float4 pv = make_float4(acc[0][j], acc[1][j], acc[2][j], acc[3][j]);
            *(float4*)&KP[k*64 + qoff] = pv;
        }
        __syncthreads();

        // O += P V
        #pragma unroll
        for (int k = 0; k < 64; k++) {
            int qoff = (ty*4 + 4*k) & 63;
            float4 av = *(const float4*)&KP[k*64 + qoff];
            float4 bv = *(const float4*)&Vs[k*64 + tx*4];
            float ar[4]={av.x,av.y,av.z,av.w}, br[4]={bv.x,bv.y,bv.z,bv.w};
            #pragma unroll
            for (int i=0;i<4;i++)
                #pragma unroll
                for (int j=0;j<4;j++)
                    Oacc[i][j] = fmaf(ar[i], br[j], Oacc[i][j]);
        }
    }

    // epilogue: normalize, store to [B,S,E] (e = h*64+d)
    #pragma unroll
    for (int i = 0; i < 4; i++) {
        float inv = 1.0f / l_i[i];
        int q = q0 + ty*4 + i;
        float4 o = make_float4(Oacc[i][0]*inv, Oacc[i][1]*inv,
                               Oacc[i][2]*inv, Oacc[i][3]*inv);
        *(float4*)&g_AO[(size_t)(b*SS + q)*EE + h*64 + tx*4] = o;
    }
}

// ---------------------------------------------------------------------------
// Output projection: out = g_AO(M,E) @ Wo(E,E)^T + bo. Same tiling as qkv.
// ---------------------------------------------------------------------------
__global__ void __launch_bounds__(256) oproj_kernel(
    const float* __restrict__ Wo, const float* __restrict__ bo,
    float* __restrict__ out)
{
    const int n0 = blockIdx.x * 64;
    const int m0 = blockIdx.y * 64;

    __shared__ float As[16][64];
    __shared__ float Bs[16][64];

    const int tid = threadIdx.x;
    const int tx = tid & 15, ty = tid >> 4;
    const int lrow = tid >> 2;
    const int lk4 = (tid & 3) << 2;

    float acc[4][4] = {};

    for (int k0 = 0; k0 < EE; k0 += 16) {
        float4 a = *(const float4*)(g_AO + (size_t)(m0 + lrow) * EE + k0 + lk4);
        float4 w = *(const float4*)(Wo   + (size_t)(n0 + lrow) * EE + k0 + lk4);
        As[lk4+0][lrow]=a.x; As[lk4+1][lrow]=a.y; As[lk4+2][lrow]=a.z; As[lk4+3][lrow]=a.w;
        Bs[lk4+0][lrow]=w.x; Bs[lk4+1][lrow]=w.y; Bs[lk4+2][lrow]=w.z; Bs[lk4+3][lrow]=w.w;
        __syncthreads();
        #pragma unroll
        for (int kk = 0; kk < 16; kk++) {
            float4 av  = *(const float4*)&As[kk][ty*4];
            float4 bv4 = *(const float4*)&Bs[kk][tx*4];
            float ar[4]={av.x,av.y,av.z,av.w};
            float br[4]={bv4.x,bv4.y,bv4.z,bv4.w};
            #pragma unroll
            for (int i=0;i<4;i++)
                #pragma unroll
                for (int j=0;j<4;j++)
                    acc[i][j] = fmaf(ar[i], br[j], acc[i][j]);
        }
        __syncthreads();
    }

    float4 bv4 = *(const float4*)(bo + n0 + tx*4);
    float bias4[4] = {bv4.x, bv4.y, bv4.z, bv4.w};
    #pragma unroll
    for (int i = 0; i < 4; i++) {
        int m = m0 + ty*4 + i;
        float4 o;
        o.x = acc[i][0] + bias4[0];
        o.y = acc[i][1] + bias4[1];
        o.z = acc[i][2] + bias4[2];
        o.w = acc[i][3] + bias4[3];
        *(float4*)(out + (size_t)m * EE + n0 + tx*4) = o;
    }
}

extern "C" void kernel_launch(void* const* d_in, const int* in_sizes, int n_in,
                              void* d_out, int out_size) {
    const float* X  = (const float*)d_in[0];
    const int*   pr = (const int*)  d_in[1];
    const int*   pc = (const int*)  d_in[2];
    const float* qw = (const float*)d_in[3];
    const float* qb = (const float*)d_in[4];
    const float* kw = (const float*)d_in[5];
    const float* kb = (const float*)d_in[6];
    const float* vw = (const float*)d_in[7];
    const float* vb = (const float*)d_in[8];
    const float* ow = (const float*)d_in[9];
    const float* ob = (const float*)d_in[10];
    const float* rt = (const float*)d_in[11];
    float* out = (float*)d_out;

    dim3 g1(EE/64, MT/64, 3);
    qkv_kernel<<<g1, 256>>>(X, qw, qb, kw, kb, vw, vb);

    dim3 g2(SS/64, HH, BB);
    attn_kernel<<<g2, 256>>>(pr, pc, rt);

    dim3 g3(EE/64, MT/64);
    oproj_kernel<<<g3, 256>>>(ow, ob, out);
}

// round 2
// speedup vs baseline: 1.0844x; 1.0844x over previous
#include <cuda_runtime.h>
#include <math.h>

#define BB 4
#define SS 1024
#define EE 768
#define HH 12
#define DD 64
#define MT (BB*SS)
#define SCALING 0.125f

// Scratch (device globals: allocation-free rule)
__device__ float g_Q[BB*HH*SS*DD];
__device__ float g_K[BB*HH*SS*DD];
__device__ float g_V[BB*HH*SS*DD];
__device__ float g_AO[BB*SS*EE];

// exp(x), FMA-pipe only (avoids MUFU bottleneck). Max rel error ~1.3e-6.
__device__ __forceinline__ float fexp(float x) {
    float t = x * 1.4426950408889634f;
    t = fmaxf(t, -125.0f);
    float fi = floorf(t);
    float f = t - fi;
    float p = 1.525273380e-5f;
    p = fmaf(p, f, 1.540353039e-4f);
    p = fmaf(p, f, 1.333355815e-3f);
    p = fmaf(p, f, 9.618129108e-3f);
    p = fmaf(p, f, 5.550410866e-2f);
    p = fmaf(p, f, 2.402265070e-1f);
    p = fmaf(p, f, 6.931471806e-1f);
    p = fmaf(p, f, 1.0f);
    int e = (int)fi;
    float s = __int_as_float((e + 127) << 23);
    return p * s;
}

// ---------------------------------------------------------------------------
// QKV projection: C = X(M,K) @ W(N,K)^T + b.  BM=BN=128, BK=16, 256 thr, 8x8.
// Output written directly in [B,H,S,D] layout. blockIdx.z selects q/k/v.
// ---------------------------------------------------------------------------
__global__ void __launch_bounds__(256) qkv_kernel(
    const float* __restrict__ X,
    const float* __restrict__ Wq, const float* __restrict__ bq,
    const float* __restrict__ Wk, const float* __restrict__ bk,
    const float* __restrict__ Wv, const float* __restrict__ bv)
{
    const int which = blockIdx.z;
    const float* Wm = (which == 0) ? Wq : (which == 1) ? Wk : Wv;
    const float* bp = (which == 0) ? bq : (which == 1) ? bk : bv;
    float* out = (which == 0) ? g_Q : (which == 1) ? g_K : g_V;
    const float scale = (which == 0) ? SCALING : 1.0f;

    const int n0 = blockIdx.x * 128;
    const int m0 = blockIdx.y * 128;

    __shared__ float As[16][128];   // [k][m]
    __shared__ float Bs[16][128];   // [k][n]

    const int tid = threadIdx.x;
    const int tx = tid & 15;            // 16 col-groups of 8
    const int ty = tid >> 4;            // 16 row-groups of 8
    const int lrow = tid & 127;         // 0..127
    const int lkh = (tid >> 7) * 8;     // 0 or 8

    const float* Ap = X  + (size_t)(m0 + lrow) * EE + lkh;
    const float* Wp = Wm + (size_t)(n0 + lrow) * EE + lkh;

    float acc[8][8] = {};

    for (int k0 = 0; k0 < EE; k0 += 16) {
        float4 a0 = *(const float4*)(Ap + k0);
        float4 a1 = *(const float4*)(Ap + k0 + 4);
        float4 w0 = *(const float4*)(Wp + k0);
        float4 w1 = *(const float4*)(Wp + k0 + 4);
        As[lkh+0][lrow]=a0.x; As[lkh+1][lrow]=a0.y; As[lkh+2][lrow]=a0.z; As[lkh+3][lrow]=a0.w;
        As[lkh+4][lrow]=a1.x; As[lkh+5][lrow]=a1.y; As[lkh+6][lrow]=a1.z; As[lkh+7][lrow]=a1.w;
        Bs[lkh+0][lrow]=w0.x; Bs[lkh+1][lrow]=w0.y; Bs[lkh+2][lrow]=w0.z; Bs[lkh+3][lrow]=w0.w;
        Bs[lkh+4][lrow]=w1.x; Bs[lkh+5][lrow]=w1.y; Bs[lkh+6][lrow]=w1.z; Bs[lkh+7][lrow]=w1.w;
        __syncthreads();
        #pragma unroll
        for (int kk = 0; kk < 16; kk++) {
            float4 x0 = *(const float4*)&As[kk][ty*8];
            float4 x1 = *(const float4*)&As[kk][ty*8+4];
            float4 y0 = *(const float4*)&Bs[kk][tx*8];
            float4 y1 = *(const float4*)&Bs[kk][tx*8+4];
            float ar[8] = {x0.x,x0.y,x0.z,x0.w,x1.x,x1.y,x1.z,x1.w};
            float br[8] = {y0.x,y0.y,y0.z,y0.w,y1.x,y1.y,y1.z,y1.w};
            #pragma unroll
            for (int i=0;i<8;i++)
                #pragma unroll
                for (int j=0;j<8;j++)
                    acc[i][j] = fmaf(ar[i], br[j], acc[i][j]);
        }
        __syncthreads();
    }

    const int ncol = n0 + tx*8;
    const int h  = ncol >> 6;
    const int d0 = ncol & 63;
    float4 bv0 = *(const float4*)(bp + ncol);
    float4 bv1 = *(const float4*)(bp + ncol + 4);
    float bias8[8] = {bv0.x,bv0.y,bv0.z,bv0.w,bv1.x,bv1.y,bv1.z,bv1.w};
    #pragma unroll
    for (int i = 0; i < 8; i++) {
        int m = m0 + ty*8 + i;
        int b = m >> 10, s = m & 1023;
        float* op = out + ((size_t)((b*HH + h)*SS + s))*DD + d0;
        float4 o0, o1;
        o0.x=(acc[i][0]+bias8[0])*scale; o0.y=(acc[i][1]+bias8[1])*scale;
        o0.z=(acc[i][2]+bias8[2])*scale; o0.w=(acc[i][3]+bias8[3])*scale;
        o1.x=(acc[i][4]+bias8[4])*scale; o1.y=(acc[i][5]+bias8[5])*scale;
        o1.z=(acc[i][6]+bias8[6])*scale; o1.w=(acc[i][7]+bias8[7])*scale;
        *(float4*)(op)     = o0;
        *(float4*)(op + 4) = o1;
    }
}

// ---------------------------------------------------------------------------
// Flash attention with relative-position bias. One CTA = (b, h, 64-row Qtile).
// 128 threads, 8x4 microtiles. Smem: Qs[d][q], KP (K^T then P), Vs (XOR-swz).
// ---------------------------------------------------------------------------
__global__ void __launch_bounds__(128) attn_kernel(
    const int* __restrict__ pos_row, const int* __restrict__ pos_col,
    const float* __restrict__ rel_table)
{
    const int q0 = blockIdx.x * 64;
    const int h  = blockIdx.y;
    const int b  = blockIdx.z;
    const float* Qp = g_Q + (size_t)(b*HH + h) * SS * DD;
    const float* Kp = g_K + (size_t)(b*HH + h) * SS * DD;
    const float* Vp = g_V + (size_t)(b*HH + h) * SS * DD;

    __shared__ float Qs[64*64];
    __shared__ float KP[64*64];
    __shared__ float Vs[64*64];

    const int tid = threadIdx.x;
    const int tx = tid & 15;        // 16 col-groups of 4
    const int ty = tid >> 4;        // 8 row-groups of 8
    const int lrow = tid & 63;      // 0..63
    const int ds0  = (tid >> 6) * 32;  // 0 or 32: column half handled

    // Q tile -> Qs transposed [d][q]
    #pragma unroll
    for (int c = 0; c < 8; c++) {
        int dd = ds0 + c*4;
        float4 v = *(const float4*)(Qp + (size_t)(q0 + lrow)*DD + dd);
        Qs[(dd+0)*64 + lrow] = v.x;
        Qs[(dd+1)*64 + lrow] = v.y;
        Qs[(dd+2)*64 + lrow] = v.z;
        Qs[(dd+3)*64 + lrow] = v.w;
    }

    // packed position keys: (row<<5)|col  (row<64, col<32)
    int rq[8];
    #pragma unroll
    for (int i = 0; i < 8; i++) {
        int q = q0 + ty*8 + i;
        rq[i] = (pos_row[b*SS + q] << 5) | pos_col[b*SS + q];
    }
    const float tb0 = rel_table[0*HH + h];
    const float tb1 = rel_table[1*HH + h];
    const float tb2 = rel_table[2*HH + h];
    const float tb3 = rel_table[3*HH + h];

    float m_i[8], l_i[8], Oacc[8][4];
    #pragma unroll
    for (int i = 0; i < 8; i++) {
        m_i[i] = -1e30f; l_i[i] = 0.f;
        #pragma unroll
        for (int j = 0; j < 4; j++) Oacc[i][j] = 0.f;
    }

    for (int kt = 0; kt < SS/64; kt++) {
        const int kb = kt * 64;
        __syncthreads();   // previous iteration's reads of KP/Vs complete

        // K tile -> KP transposed [d][k]; V tile -> Vs [k][d^swz]
        #pragma unroll
        for (int c = 0; c < 8; c++) {
            int dd = ds0 + c*4;
            float4 v = *(const float4*)(Kp + (size_t)(kb + lrow)*DD + dd);
            KP[(dd+0)*64 + lrow] = v.x;
            KP[(dd+1)*64 + lrow] = v.y;
            KP[(dd+2)*64 + lrow] = v.z;
            KP[(dd+3)*64 + lrow] = v.w;
            float4 vv = *(const float4*)(Vp + (size_t)(kb + lrow)*DD + dd);
            *(float4*)&Vs[lrow*64 + (dd ^ ((lrow & 15) * 4))] = vv;
        }
        __syncthreads();

        // S = Q K^T (64x64 tile), 8x4 per thread
        float acc[8][4] = {};
        #pragma unroll
        for (int d = 0; d < 64; d++) {
            float4 a0 = *(const float4*)&Qs[d*64 + ty*8];
            float4 a1 = *(const float4*)&Qs[d*64 + ty*8 + 4];
            float4 bv = *(const float4*)&KP[d*64 + tx*4];
            float ar[8] = {a0.x,a0.y,a0.z,a0.w,a1.x,a1.y,a1.z,a1.w};
            float br[4] = {bv.x,bv.y,bv.z,bv.w};
            #pragma unroll
            for (int i=0;i<8;i++)
                #pragma unroll
                for (int j=0;j<4;j++)
                    acc[i][j] = fmaf(ar[i], br[j], acc[i][j]);
        }

        // relative-position bias
        int rk[4];
        #pragma unroll
        for (int j = 0; j < 4; j++) {
            int k = kb + tx*4 + j;
            rk[j] = (pos_row[b*SS + k] << 5) | pos_col[b*SS + k];
        }
        #pragma unroll
        for (int i = 0; i < 8; i++)
            #pragma unroll
            for (int j = 0; j < 4; j++) {
                int x = rq[i] ^ rk[j];
                bool r0 = (x < 32);          // rows equal
                bool c0 = ((x & 31) == 0);   // cols equal
                float bias = r0 ? (c0 ? tb3 : tb1) : (c0 ? tb2 : tb0);
                acc[i][j] += bias;
            }

        // online softmax (row groups = 16 lanes sharing ty)
        #pragma unroll
        for (int i = 0; i < 8; i++) {
            float mx = fmaxf(fmaxf(acc[i][0], acc[i][1]), fmaxf(acc[i][2], acc[i][3]));
            #pragma unroll
            for (int off = 8; off > 0; off >>= 1)
                mx = fmaxf(mx, __shfl_xor_sync(0xffffffffu, mx, off));
            float mnew = fmaxf(m_i[i], mx);
            float sc = fexp(m_i[i] - mnew);
            m_i[i] = mnew;
            float rs = 0.f;
            #pragma unroll
            for (int j = 0; j < 4; j++) {
                acc[i][j] = fexp(acc[i][j] - mnew);
                rs += acc[i][j];
            }
            #pragma unroll
            for (int off = 8; off > 0; off >>= 1)
                rs += __shfl_xor_sync(0xffffffffu, rs, off);
            l_i[i] = l_i[i] * sc + rs;
            #pragma unroll
            for (int j = 0; j < 4; j++) Oacc[i][j] *= sc;
        }

        __syncthreads();   // done reading K from KP

        // P -> KP as [k][q ^ swz]
        #pragma unroll
        for (int j = 0; j < 4; j++) {
            int k = tx*4 + j;
            int sw = (k & 15) * 4;
            *(float4*)&KP[k*64 + ((ty*8)     ^ sw)] =
                make_float4(acc[0][j], acc[1][j], acc[2][j], acc[3][j]);
            *(float4*)&KP[k*64 + ((ty*8 + 4) ^ sw)] =
                make_float4(acc[4][j], acc[5][j], acc[6][j], acc[7][j]);
        }
        __syncthreads();

        // O += P V
        #pragma unroll
        for (int k = 0; k < 64; k++) {
            int sw = (k & 15) * 4;
            float4 p0 = *(const float4*)&KP[k*64 + ((ty*8)     ^ sw)];
            float4 p1 = *(const float4*)&KP[k*64 + ((ty*8 + 4) ^ sw)];
            float4 vv = *(const float4*)&Vs[k*64 + ((tx*4) ^ sw)];
            float pr[8] = {p0.x,p0.y,p0.z,p0.w,p1.x,p1.y,p1.z,p1.w};
            float vr[4] = {vv.x,vv.y,vv.z,vv.w};
            #pragma unroll
            for (int i=0;i<8;i++)
                #pragma unroll
                for (int j=0;j<4;j++)
                    Oacc[i][j] = fmaf(pr[i], vr[j], Oacc[i][j]);
        }
    }

    // epilogue: normalize, store to [B,S,E] (e = h*64+d)
    #pragma unroll
    for (int i = 0; i < 8; i++) {
        float inv = 1.0f / l_i[i];
        int q = q0 + ty*8 + i;
        float4 o = make_float4(Oacc[i][0]*inv, Oacc[i][1]*inv,
                               Oacc[i][2]*inv, Oacc[i][3]*inv);
        *(float4*)&g_AO[(size_t)(b*SS + q)*EE + h*64 + tx*4] = o;
    }
}

// ---------------------------------------------------------------------------
// Output projection: out = g_AO(M,E) @ Wo(E,E)^T + bo. Same tiling as qkv.
// ---------------------------------------------------------------------------
__global__ void __launch_bounds__(256) oproj_kernel(
    const float* __restrict__ Wo, const float* __restrict__ bo,
    float* __restrict__ out)
{
    const int n0 = blockIdx.x * 128;
    const int m0 = blockIdx.y * 128;

    __shared__ float As[16][128];
    __shared__ float Bs[16][128];

    const int tid = threadIdx.x;
    const int tx = tid & 15;
    const int ty = tid >> 4;
    const int lrow = tid & 127;
    const int lkh = (tid >> 7) * 8;

    const float* Ap = g_AO + (size_t)(m0 + lrow) * EE + lkh;
    const float* Wp = Wo   + (size_t)(n0 + lrow) * EE + lkh;

    float acc[8][8] = {};

    for (int k0 = 0; k0 < EE; k0 += 16) {
        float4 a0 = *(const float4*)(Ap + k0);
        float4 a1 = *(const float4*)(Ap + k0 + 4);
        float4 w0 = *(const float4*)(Wp + k0);
        float4 w1 = *(const float4*)(Wp + k0 + 4);
        As[lkh+0][lrow]=a0.x; As[lkh+1][lrow]=a0.y; As[lkh+2][lrow]=a0.z; As[lkh+3][lrow]=a0.w;
        As[lkh+4][lrow]=a1.x; As[lkh+5][lrow]=a1.y; As[lkh+6][lrow]=a1.z; As[lkh+7][lrow]=a1.w;
        Bs[lkh+0][lrow]=w0.x; Bs[lkh+1][lrow]=w0.y; Bs[lkh+2][lrow]=w0.z; Bs[lkh+3][lrow]=w0.w;
        Bs[lkh+4][lrow]=w1.x; Bs[lkh+5][lrow]=w1.y; Bs[lkh+6][lrow]=w1.z; Bs[lkh+7][lrow]=w1.w;
        __syncthreads();
        #pragma unroll
        for (int kk = 0; kk < 16; kk++) {
            float4 x0 = *(const float4*)&As[kk][ty*8];
            float4 x1 = *(const float4*)&As[kk][ty*8+4];
            float4 y0 = *(const float4*)&Bs[kk][tx*8];
            float4 y1 = *(const float4*)&Bs[kk][tx*8+4];
            float ar[8] = {x0.x,x0.y,x0.z,x0.w,x1.x,x1.y,x1.z,x1.w};
            float br[8] = {y0.x,y0.y,y0.z,y0.w,y1.x,y1.y,y1.z,y1.w};
            #pragma unroll
            for (int i=0;i<8;i++)
                #pragma unroll
                for (int j=0;j<8;j++)
                    acc[i][j] = fmaf(ar[i], br[j], acc[i][j]);
        }
        __syncthreads();
    }

    float4 bv0 = *(const float4*)(bo + n0 + tx*8);
    float4 bv1 = *(const float4*)(bo + n0 + tx*8 + 4);
    float bias8[8] = {bv0.x,bv0.y,bv0.z,bv0.w,bv1.x,bv1.y,bv1.z,bv1.w};
    #pragma unroll
    for (int i = 0; i < 8; i++) {
        int m = m0 + ty*8 + i;
        float* op = out + (size_t)m * EE + n0 + tx*8;
        float4 o0, o1;
        o0.x=acc[i][0]+bias8[0]; o0.y=acc[i][1]+bias8[1];
        o0.z=acc[i][2]+bias8[2]; o0.w=acc[i][3]+bias8[3];
        o1.x=acc[i][4]+bias8[4]; o1.y=acc[i][5]+bias8[5];
        o1.z=acc[i][6]+bias8[6]; o1.w=acc[i][7]+bias8[7];
        *(float4*)(op)     = o0;
        *(float4*)(op + 4) = o1;
    }
}

extern "C" void kernel_launch(void* const* d_in, const int* in_sizes, int n_in,
                              void* d_out, int out_size) {
    const float* X  = (const float*)d_in[0];
    const int*   pr = (const int*)  d_in[1];
    const int*   pc = (const int*)  d_in[2];
    const float* qw = (const float*)d_in[3];
    const float* qb = (const float*)d_in[4];
    const float* kw = (const float*)d_in[5];
    const float* kb = (const float*)d_in[6];
    const float* vw = (const float*)d_in[7];
    const float* vb = (const float*)d_in[8];
    const float* ow = (const float*)d_in[9];
    const float* ob = (const float*)d_in[10];
    const float* rt = (const float*)d_in[11];
    float* out = (float*)d_out;

    dim3 g1(EE/128, MT/128, 3);
    qkv_kernel<<<g1, 256>>>(X, qw, qb, kw, kb, vw, vb);

    dim3 g2(SS/64, HH, BB);
    attn_kernel<<<g2, 128>>>(pr, pc, rt);

    dim3 g3(EE/128, MT/128);
    oproj_kernel<<<g3, 256>>>(ow, ob, out);
}

// round 4
// speedup vs baseline: 1.7178x; 1.5841x over previous
#include <cuda_runtime.h>
#include <cuda_bf16.h>
#include <cstdint>
#include <math.h>

#define BB 4
#define SS 1024
#define EE 768
#define HH 12
#define DD 64
#define MT (BB*SS)
#define SCALING 0.125f

// ---------------- device scratch (allocation-free rule) ----------------
__device__ float g_Q[BB*HH*SS*DD];
__device__ float g_K[BB*HH*SS*DD];
__device__ float g_V[BB*HH*SS*DD];
__device__ __nv_bfloat16 g_Xhi[MT*EE],  g_Xlo[MT*EE];
__device__ __nv_bfloat16 g_Whi[4*EE*EE], g_Wlo[4*EE*EE];
__device__ __nv_bfloat16 g_AOhi[MT*EE], g_AOlo[MT*EE];

__device__ __forceinline__ uint32_t smem_u32(const void* p) {
    uint32_t a;
    asm("{ .reg .u64 t; cvta.to.shared.u64 t, %1; cvt.u32.u64 %0, t; }"
        : "=r"(a) : "l"(p));
    return a;
}

#define LDSM4(r, addr) \
    asm volatile("ldmatrix.sync.aligned.m8n8.x4.shared.b16 {%0,%1,%2,%3}, [%4];" \
        : "=r"((r)[0]), "=r"((r)[1]), "=r"((r)[2]), "=r"((r)[3]) : "r"(addr))

#define MMA_BF16(d, a, b0v, b1v) \
    asm volatile("mma.sync.aligned.m16n8k16.row.col.f32.bf16.bf16.f32 " \
        "{%0,%1,%2,%3}, {%4,%5,%6,%7}, {%8,%9}, {%0,%1,%2,%3};" \
        : "+f"((d)[0]), "+f"((d)[1]), "+f"((d)[2]), "+f"((d)[3]) \
        : "r"((a)[0]), "r"((a)[1]), "r"((a)[2]), "r"((a)[3]), "r"(b0v), "r"(b1v))

#define CP_ASYNC16(smem, gmem) \
    asm volatile("cp.async.cg.shared.global [%0], [%1], 16;" :: "r"(smem), "l"(gmem))
#define CP_COMMIT()  asm volatile("cp.async.commit_group;" ::: "memory")
#define CP_WAIT0()   asm volatile("cp.async.wait_group 0;" ::: "memory")

// exp(x), FMA-pipe only. Max rel error ~1.3e-6.
__device__ __forceinline__ float fexp(float x) {
    float t = x * 1.4426950408889634f;
    t = fmaxf(t, -125.0f);
    float fi = floorf(t);
    float f = t - fi;
    float p = 1.525273380e-5f;
    p = fmaf(p, f, 1.540353039e-4f);
    p = fmaf(p, f, 1.333355815e-3f);
    p = fmaf(p, f, 9.618129108e-3f);
    p = fmaf(p, f, 5.550410866e-2f);
    p = fmaf(p, f, 2.402265070e-1f);
    p = fmaf(p, f, 6.931471806e-1f);
    p = fmaf(p, f, 1.0f);
    int e = (int)fi;
    float s = __int_as_float((e + 127) << 23);
    return p * s;
}

// ---------------------------------------------------------------------------
// fp32 -> (bf16 hi, bf16 lo) split kernels
// ---------------------------------------------------------------------------
__global__ void __launch_bounds__(256) splitX_kernel(const float* __restrict__ src) {
    int i = (blockIdx.x * 256 + threadIdx.x) * 4;
    float4 v = *(const float4*)(src + i);
    float xs[4] = {v.x, v.y, v.z, v.w};
    #pragma unroll
    for (int j = 0; j < 4; j++) {
        __nv_bfloat16 hv = __float2bfloat16(xs[j]);
        g_Xhi[i+j] = hv;
        g_Xlo[i+j] = __float2bfloat16(xs[j] - __bfloat162float(hv));
    }
}
__global__ void __launch_bounds__(256) splitW_kernel(const float* __restrict__ src, int slot) {
    int i = (blockIdx.x * 256 + threadIdx.x) * 4;
    float4 v = *(const float4*)(src + i);
    float xs[4] = {v.x, v.y, v.z, v.w};
    size_t o = (size_t)slot * EE * EE + i;
    #pragma unroll
    for (int j = 0; j < 4; j++) {
        __nv_bfloat16 hv = __float2bfloat16(xs[j]);
        g_Whi[o+j] = hv;
        g_Wlo[o+j] = __float2bfloat16(xs[j] - __bfloat162float(hv));
    }
}

// ---------------------------------------------------------------------------
// HMMA GEMM: D = A(M,K) @ W(N,K)^T via 3x bf16-split mma.sync, fp32 accum.
// CTA 128x128, 8 warps (2x4), warp tile 64x32, BK=64, double-buffered cp.async.
// Smem tile layout: [row][64 bf16] with (chunk ^ (row&7)) 16B XOR swizzle.
// is_qkv=1: A=g_X{hi,lo}, W slot z=blockIdx.z, out=g_Q/K/V in [B,H,S,D] (+bias,scale)
// is_qkv=0: A=g_AO{hi,lo}, W slot 3, out=outp row-major [M,E] (+bias)
// ---------------------------------------------------------------------------
__global__ void __launch_bounds__(256) gemm_mma_kernel(
    const float* __restrict__ b0p, const float* __restrict__ b1p,
    const float* __restrict__ b2p, float* __restrict__ outp,
    int wslot0, int is_qkv)
{
    extern __shared__ char dsm[];
    const uint32_t sbase = smem_u32(dsm);

    const int tid = threadIdx.x;
    const int wid = tid >> 5, lane = tid & 31;
    const int warp_m = wid & 1, warp_n = wid >> 1;
    const int m0w = warp_m * 64, n0w = warp_n * 32;

    const int z = is_qkv ? blockIdx.z : 0;
    const size_t woff = (size_t)(wslot0 + z) * EE * EE;
    const float* bias = (z == 0) ? b0p : (z == 1) ? b1p : b2p;
    const float scale = (is_qkv && z == 0) ? SCALING : 1.0f;
    float* out = is_qkv ? (z == 0 ? g_Q : (z == 1 ? g_K : g_V)) : outp;

    const int n0 = blockIdx.x * 128;
    const int m0 = blockIdx.y * 128;

    const __nv_bfloat16* s0 = (is_qkv ? g_Xhi : g_AOhi) + (size_t)m0 * EE;
    const __nv_bfloat16* s1 = (is_qkv ? g_Xlo : g_AOlo) + (size_t)m0 * EE;
    const __nv_bfloat16* s2 = g_Whi + woff + (size_t)n0 * EE;
    const __nv_bfloat16* s3 = g_Wlo + woff + (size_t)n0 * EE;

    // loader: stage = 4 tiles (Ahi,Alo,Bhi,Blo) of [128 x 64 bf16] = 64KB
    const int lrow = tid >> 3;           // 0..31 base row (4 uint4 per tile)
    const int lch  = tid & 7;            // chunk 0..7
    auto stage_load = [&](int k0, int stg) {
        uint32_t sb = sbase + (uint32_t)stg * 65536u;
        #pragma unroll
        for (int t = 0; t < 4; t++) {
            const __nv_bfloat16* sp = (t==0?s0:t==1?s1:t==2?s2:s3) + k0 + lch*8;
            uint32_t tb = sb + (uint32_t)t * 16384u;
            #pragma unroll
            for (int j = 0; j < 4; j++) {
                int row = lrow + j*32;
                CP_ASYNC16(tb + row*128 + ((lch ^ (row & 7)) << 4),
                           sp + (size_t)row * EE);
            }
        }
        CP_COMMIT();
    };

    // per-lane ldmatrix row offsets (swizzle uses lane&7 == row&7)
    const int l7 = lane & 7;
    uint32_t aoff[4], boff[2];
    #pragma unroll
    for (int t = 0; t < 4; t++)
        aoff[t] = (uint32_t)(m0w + t*16 + (lane & 15)) * 128u;
    #pragma unroll
    for (int p = 0; p < 2; p++)
        boff[p] = (uint32_t)(n0w + p*16 + l7 + ((lane >> 4) << 3)) * 128u;
    const int achk = lane >> 4;          // +0/+1 chunk within k16 for A
    const int bchk = (lane >> 3) & 1;    // for B

    float acc[4][4][4] = {};

    stage_load(0, 0);

    #pragma unroll 1
    for (int s = 0; s < EE/64; s++) {
        CP_WAIT0();
        __syncthreads();
        if (s + 1 < EE/64) stage_load((s + 1) * 64, (s + 1) & 1);

        const uint32_t stg = sbase + (uint32_t)(s & 1) * 65536u;
        const uint32_t Ahi = stg, Alo = stg + 16384u;
        const uint32_t Bhi = stg + 32768u, Blo = stg + 49152u;

        #pragma unroll
        for (int ks = 0; ks < 4; ks++) {
            const uint32_t asw = (uint32_t)((2*ks + achk) ^ l7) << 4;
            const uint32_t bsw = (uint32_t)((2*ks + bchk) ^ l7) << 4;
            uint32_t Ah[4][4], Al[4][4], Bh[2][4], Bl[2][4];
            #pragma unroll
            for (int t = 0; t < 4; t++) {
                LDSM4(Ah[t], Ahi + aoff[t] + asw);
                LDSM4(Al[t], Alo + aoff[t] + asw);
            }
            #pragma unroll
            for (int p = 0; p < 2; p++) {
                LDSM4(Bh[p], Bhi + boff[p] + bsw);
                LDSM4(Bl[p], Blo + boff[p] + bsw);
            }
            #pragma unroll
            for (int t = 0; t < 4; t++)
                #pragma unroll
                for (int n = 0; n < 4; n++) {
                    const int p = n >> 1, q = (n & 1) * 2;
                    MMA_BF16(acc[t][n], Ah[t], Bh[p][q], Bh[p][q+1]);
                    MMA_BF16(acc[t][n], Ah[t], Bl[p][q], Bl[p][q+1]);
                    MMA_BF16(acc[t][n], Al[t], Bh[p][q], Bh[p][q+1]);
                }
        }
        __syncthreads();
    }

    // epilogue
    const int rl = lane >> 2, cl = (lane & 3) * 2;
    #pragma unroll
    for (int t = 0; t < 4; t++)
        #pragma unroll
        for (int n = 0; n < 4; n++) {
            const int col = n0 + n0w + n*8 + cl;
            #pragma unroll
            for (int half = 0; half < 2; half++) {
                const int row = m0 + m0w + t*16 + rl + half*8;
                float2 o;
                o.x = (acc[t][n][half*2+0] + bias[col+0]) * scale;
                o.y = (acc[t][n][half*2+1] + bias[col+1]) * scale;
                if (is_qkv) {
                    const int hh = col >> 6, d0 = col & 63;
                    const int bb_ = row >> 10, ss_ = row & 1023;
                    *(float2*)(out + ((size_t)((bb_*HH + hh)*SS + ss_))*DD + d0) = o;
                } else {
                    *(float2*)(out + (size_t)row * EE + col) = o;
                }
            }
        }
}

// ---------------------------------------------------------------------------
// Flash attention with relative-position bias (SIMT fp32, proven core).
// Epilogue emits AO as bf16 hi/lo for the tensor-core output projection.
// ---------------------------------------------------------------------------
__global__ void __launch_bounds__(128) attn_kernel(
    const int* __restrict__ pos_row, const int* __restrict__ pos_col,
    const float* __restrict__ rel_table)
{
    const int q0 = blockIdx.x * 64;
    const int h  = blockIdx.y;
    const int b  = blockIdx.z;
    const float* Qp = g_Q + (size_t)(b*HH + h) * SS * DD;
    const float* Kp = g_K + (size_t)(b*HH + h) * SS * DD;
    const float* Vp = g_V + (size_t)(b*HH + h) * SS * DD;

    __shared__ float Qs[64*64];
    __shared__ float KP[64*64];
    __shared__ float Vs[64*64];

    const int tid = threadIdx.x;
    const int tx = tid & 15;
    const int ty = tid >> 4;
    const int lrow = tid & 63;
    const int ds0  = (tid >> 6) * 32;

    #pragma unroll
    for (int c = 0; c < 8; c++) {
        int dd = ds0 + c*4;
        float4 v = *(const float4*)(Qp + (size_t)(q0 + lrow)*DD + dd);
        Qs[(dd+0)*64 + lrow] = v.x;
        Qs[(dd+1)*64 + lrow] = v.y;
        Qs[(dd+2)*64 + lrow] = v.z;
        Qs[(dd+3)*64 + lrow] = v.w;
    }

    int rq[8];
    #pragma unroll
    for (int i = 0; i < 8; i++) {
        int q = q0 + ty*8 + i;
        rq[i] = (pos_row[b*SS + q] << 5) | pos_col[b*SS + q];
    }
    const float tb0 = rel_table[0*HH + h];
    const float tb1 = rel_table[1*HH + h];
    const float tb2 = rel_table[2*HH + h];
    const float tb3 = rel_table[3*HH + h];

    float m_i[8], l_i[8], Oacc[8][4];
    #pragma unroll
    for (int i = 0; i < 8; i++) {
        m_i[i] = -1e30f; l_i[i] = 0.f;
        #pragma unroll
        for (int j = 0; j < 4; j++) Oacc[i][j] = 0.f;
    }

    for (int kt = 0; kt < SS/64; kt++) {
        const int kb = kt * 64;
        __syncthreads();

        #pragma unroll
        for (int c = 0; c < 8; c++) {
            int dd = ds0 + c*4;
            float4 v = *(const float4*)(Kp + (size_t)(kb + lrow)*DD + dd);
            KP[(dd+0)*64 + lrow] = v.x;
            KP[(dd+1)*64 + lrow] = v.y;
            KP[(dd+2)*64 + lrow] = v.z;
            KP[(dd+3)*64 + lrow] = v.w;
            float4 vv = *(const float4*)(Vp + (size_t)(kb + lrow)*DD + dd);
            *(float4*)&Vs[lrow*64 + (dd ^ ((lrow & 15) * 4))] = vv;
        }
        __syncthreads();

        float acc[8][4] = {};
        #pragma unroll
        for (int d = 0; d < 64; d++) {
            float4 a0 = *(const float4*)&Qs[d*64 + ty*8];
            float4 a1 = *(const float4*)&Qs[d*64 + ty*8 + 4];
            float4 bv = *(const float4*)&KP[d*64 + tx*4];
            float ar[8] = {a0.x,a0.y,a0.z,a0.w,a1.x,a1.y,a1.z,a1.w};
            float br[4] = {bv.x,bv.y,bv.z,bv.w};
            #pragma unroll
            for (int i=0;i<8;i++)
                #pragma unroll
                for (int j=0;j<4;j++)
                    acc[i][j] = fmaf(ar[i], br[j], acc[i][j]);
        }

        int rk[4];
        #pragma unroll
        for (int j = 0; j < 4; j++) {
            int k = kb + tx*4 + j;
            rk[j] = (pos_row[b*SS + k] << 5) | pos_col[b*SS + k];
        }
        #pragma unroll
        for (int i = 0; i < 8; i++)
            #pragma unroll
            for (int j = 0; j < 4; j++) {
                int x = rq[i] ^ rk[j];
                bool r0 = (x < 32);
                bool c0 = ((x & 31) == 0);
                float bias = r0 ? (c0 ? tb3 : tb1) : (c0 ? tb2 : tb0);
                acc[i][j] += bias;
            }

        #pragma unroll
        for (int i = 0; i < 8; i++) {
            float mx = fmaxf(fmaxf(acc[i][0], acc[i][1]), fmaxf(acc[i][2], acc[i][3]));
            #pragma unroll
            for (int off = 8; off > 0; off >>= 1)
                mx = fmaxf(mx, __shfl_xor_sync(0xffffffffu, mx, off));
            float mnew = fmaxf(m_i[i], mx);
            float sc = fexp(m_i[i] - mnew);
            m_i[i] = mnew;
            float rs = 0.f;
            #pragma unroll
            for (int j = 0; j < 4; j++) {
                acc[i][j] = fexp(acc[i][j] - mnew);
                rs += acc[i][j];
            }
            #pragma unroll
            for (int off = 8; off > 0; off >>= 1)
                rs += __shfl_xor_sync(0xffffffffu, rs, off);
            l_i[i] = l_i[i] * sc + rs;
            #pragma unroll
            for (int j = 0; j < 4; j++) Oacc[i][j] *= sc;
        }

        __syncthreads();

        #pragma unroll
        for (int j = 0; j < 4; j++) {
            int k = tx*4 + j;
            int sw = (k & 15) * 4;
            *(float4*)&KP[k*64 + ((ty*8)     ^ sw)] =
                make_float4(acc[0][j], acc[1][j], acc[2][j], acc[3][j]);
            *(float4*)&KP[k*64 + ((ty*8 + 4) ^ sw)] =
                make_float4(acc[4][j], acc[5][j], acc[6][j], acc[7][j]);
        }
        __syncthreads();

        #pragma unroll
        for (int k = 0; k < 64; k++) {
            int sw = (k & 15) * 4;
            float4 p0 = *(const float4*)&KP[k*64 + ((ty*8)     ^ sw)];
            float4 p1 = *(const float4*)&KP[k*64 + ((ty*8 + 4) ^ sw)];
            float4 vv = *(const float4*)&Vs[k*64 + ((tx*4) ^ sw)];
            float pr[8] = {p0.x,p0.y,p0.z,p0.w,p1.x,p1.y,p1.z,p1.w};
            float vr[4] = {vv.x,vv.y,vv.z,vv.w};
            #pragma unroll
            for (int i=0;i<8;i++)
                #pragma unroll
                for (int j=0;j<4;j++)
                    Oacc[i][j] = fmaf(pr[i], vr[j], Oacc[i][j]);
        }
    }

    #pragma unroll
    for (int i = 0; i < 8; i++) {
        float inv = 1.0f / l_i[i];
        int q = q0 + ty*8 + i;
        size_t base = (size_t)(b*SS + q)*EE + h*64 + tx*4;
        #pragma unroll
        for (int j = 0; j < 4; j++) {
            float o = Oacc[i][j] * inv;
            __nv_bfloat16 oh = __float2bfloat16(o);
            g_AOhi[base + j] = oh;
            g_AOlo[base + j] = __float2bfloat16(o - __bfloat162float(oh));
        }
    }
}

// ---------------------------------------------------------------------------
extern "C" void kernel_launch(void* const* d_in, const int* in_sizes, int n_in,
                              void* d_out, int out_size) {
    const float* X  = (const float*)d_in[0];
    const int*   pr = (const int*)  d_in[1];
    const int*   pc = (const int*)  d_in[2];
    const float* qw = (const float*)d_in[3];
    const float* qb = (const float*)d_in[4];
    const float* kw = (const float*)d_in[5];
    const float* kb = (const float*)d_in[6];
    const float* vw = (const float*)d_in[7];
    const float* vb = (const float*)d_in[8];
    const float* ow = (const float*)d_in[9];
    const float* ob = (const float*)d_in[10];
    const float* rt = (const float*)d_in[11];
    float* out = (float*)d_out;

    const int DSMEM = 2 * 65536;   // double-buffered 4x16KB tiles
    cudaFuncSetAttribute(gemm_mma_kernel,
                         cudaFuncAttributeMaxDynamicSharedMemorySize, DSMEM);

    splitX_kernel<<<MT*EE/1024, 256>>>(X);
    splitW_kernel<<<EE*EE/1024, 256>>>(qw, 0);
    splitW_kernel<<<EE*EE/1024, 256>>>(kw, 1);
    splitW_kernel<<<EE*EE/1024, 256>>>(vw, 2);
    splitW_kernel<<<EE*EE/1024, 256>>>(ow, 3);

    dim3 g1(EE/128, MT/128, 3);
    gemm_mma_kernel<<<g1, 256, DSMEM>>>(qb, kb, vb, nullptr, 0, 1);

    dim3 g2(SS/64, HH, BB);
    attn_kernel<<<g2, 128>>>(pr, pc, rt);

    dim3 g3(EE/128, MT/128, 1);
    gemm_mma_kernel<<<g3, 256, DSMEM>>>(ob, ob, ob, out, 3, 0);
}

// round 5
// speedup vs baseline: 2.8255x; 1.6448x over previous
#include <cuda_runtime.h>
#include <cuda_bf16.h>
#include <cstdint>
#include <math.h>

#define BB 4
#define SS 1024
#define EE 768
#define HH 12
#define DD 64
#define MT (BB*SS)
#define SCALING 0.125f

// ---------------- device scratch (allocation-free rule) ----------------
__device__ __nv_bfloat16 g_Qhi[BB*HH*SS*DD], g_Qlo[BB*HH*SS*DD];
__device__ __nv_bfloat16 g_Khi[BB*HH*SS*DD], g_Klo[BB*HH*SS*DD];
__device__ __nv_bfloat16 g_Vhi[BB*HH*SS*DD], g_Vlo[BB*HH*SS*DD];
__device__ __nv_bfloat16 g_Xhi[MT*EE],  g_Xlo[MT*EE];
__device__ __nv_bfloat16 g_Whi[4*EE*EE], g_Wlo[4*EE*EE];
__device__ __nv_bfloat16 g_AOhi[MT*EE], g_AOlo[MT*EE];

__device__ __forceinline__ uint32_t smem_u32(const void* p) {
    uint32_t a;
    asm("{ .reg .u64 t; cvta.to.shared.u64 t, %1; cvt.u32.u64 %0, t; }"
        : "=r"(a) : "l"(p));
    return a;
}

#define LDSM4(r, addr) \
    asm volatile("ldmatrix.sync.aligned.m8n8.x4.shared.b16 {%0,%1,%2,%3}, [%4];" \
        : "=r"((r)[0]), "=r"((r)[1]), "=r"((r)[2]), "=r"((r)[3]) : "r"(addr))
#define LDSM4T(r, addr) \
    asm volatile("ldmatrix.sync.aligned.m8n8.x4.trans.shared.b16 {%0,%1,%2,%3}, [%4];" \
        : "=r"((r)[0]), "=r"((r)[1]), "=r"((r)[2]), "=r"((r)[3]) : "r"(addr))

#define MMA_BF16(d, a, b0v, b1v) \
    asm volatile("mma.sync.aligned.m16n8k16.row.col.f32.bf16.bf16.f32 " \
        "{%0,%1,%2,%3}, {%4,%5,%6,%7}, {%8,%9}, {%0,%1,%2,%3};" \
        : "+f"((d)[0]), "+f"((d)[1]), "+f"((d)[2]), "+f"((d)[3]) \
        : "r"((a)[0]), "r"((a)[1]), "r"((a)[2]), "r"((a)[3]), "r"(b0v), "r"(b1v))

#define CP_ASYNC16(smem, gmem) \
    asm volatile("cp.async.cg.shared.global [%0], [%1], 16;" :: "r"(smem), "l"(gmem))
#define CP_COMMIT()  asm volatile("cp.async.commit_group;" ::: "memory")
#define CP_WAIT0()   asm volatile("cp.async.wait_group 0;" ::: "memory")
#define CP_WAIT1()   asm volatile("cp.async.wait_group 1;" ::: "memory")

// pack 2 fp32 -> bf16x2 hi + bf16x2 lo (3-split residual)
__device__ __forceinline__ void splitpack(float x, float y, uint32_t& hi, uint32_t& lo) {
    __nv_bfloat16 hx = __float2bfloat16(x), hy = __float2bfloat16(y);
    __nv_bfloat162 H; H.x = hx; H.y = hy;
    __nv_bfloat162 L;
    L.x = __float2bfloat16(x - __bfloat162float(hx));
    L.y = __float2bfloat16(y - __bfloat162float(hy));
    hi = *(uint32_t*)&H;
    lo = *(uint32_t*)&L;
}

// exp(x), FMA-pipe only. Max rel error ~1.3e-6.
__device__ __forceinline__ float fexp(float x) {
    float t = x * 1.4426950408889634f;
    t = fmaxf(t, -125.0f);
    float fi = floorf(t);
    float f = t - fi;
    float p = 1.525273380e-5f;
    p = fmaf(p, f, 1.540353039e-4f);
    p = fmaf(p, f, 1.333355815e-3f);
    p = fmaf(p, f, 9.618129108e-3f);
    p = fmaf(p, f, 5.550410866e-2f);
    p = fmaf(p, f, 2.402265070e-1f);
    p = fmaf(p, f, 6.931471806e-1f);
    p = fmaf(p, f, 1.0f);
    int e = (int)fi;
    float s = __int_as_float((e + 127) << 23);
    return p * s;
}

// ---------------------------------------------------------------------------
// fp32 -> (bf16 hi, bf16 lo) split kernels
// ---------------------------------------------------------------------------
__global__ void __launch_bounds__(256) splitX_kernel(const float* __restrict__ src) {
    int i = (blockIdx.x * 256 + threadIdx.x) * 4;
    float4 v = *(const float4*)(src + i);
    float xs[4] = {v.x, v.y, v.z, v.w};
    #pragma unroll
    for (int j = 0; j < 4; j++) {
        __nv_bfloat16 hv = __float2bfloat16(xs[j]);
        g_Xhi[i+j] = hv;
        g_Xlo[i+j] = __float2bfloat16(xs[j] - __bfloat162float(hv));
    }
}
__global__ void __launch_bounds__(256) splitW_kernel(const float* __restrict__ src, int slot) {
    int i = (blockIdx.x * 256 + threadIdx.x) * 4;
    float4 v = *(const float4*)(src + i);
    float xs[4] = {v.x, v.y, v.z, v.w};
    size_t o = (size_t)slot * EE * EE + i;
    #pragma unroll
    for (int j = 0; j < 4; j++) {
        __nv_bfloat16 hv = __float2bfloat16(xs[j]);
        g_Whi[o+j] = hv;
        g_Wlo[o+j] = __float2bfloat16(xs[j] - __bfloat162float(hv));
    }
}

// ---------------------------------------------------------------------------
// HMMA GEMM: D = A(M,K) @ W(N,K)^T via 3x bf16-split mma.sync, fp32 accum.
// CTA 128x128, 8 warps (2x4), warp tile 64x32, BK=64, double-buffered cp.async.
// is_qkv=1: out = bf16 hi/lo Q/K/V in [B,H,S,D] (+bias, Q scaled)
// is_qkv=0: out = outp fp32 row-major [M,E] (+bias)
// ---------------------------------------------------------------------------
__global__ void __launch_bounds__(256) gemm_mma_kernel(
    const float* __restrict__ b0p, const float* __restrict__ b1p,
    const float* __restrict__ b2p, float* __restrict__ outp,
    int wslot0, int is_qkv)
{
    extern __shared__ char dsm[];
    const uint32_t sbase = smem_u32(dsm);

    const int tid = threadIdx.x;
    const int wid = tid >> 5, lane = tid & 31;
    const int warp_m = wid & 1, warp_n = wid >> 1;
    const int m0w = warp_m * 64, n0w = warp_n * 32;

    const int z = is_qkv ? blockIdx.z : 0;
    const size_t woff = (size_t)(wslot0 + z) * EE * EE;
    const float* bias = (z == 0) ? b0p : (z == 1) ? b1p : b2p;
    const float scale = (is_qkv && z == 0) ? SCALING : 1.0f;
    __nv_bfloat16* outHi = (z == 0) ? g_Qhi : (z == 1) ? g_Khi : g_Vhi;
    __nv_bfloat16* outLo = (z == 0) ? g_Qlo : (z == 1) ? g_Klo : g_Vlo;

    const int n0 = blockIdx.x * 128;
    const int m0 = blockIdx.y * 128;

    const __nv_bfloat16* s0 = (is_qkv ? g_Xhi : g_AOhi) + (size_t)m0 * EE;
    const __nv_bfloat16* s1 = (is_qkv ? g_Xlo : g_AOlo) + (size_t)m0 * EE;
    const __nv_bfloat16* s2 = g_Whi + woff + (size_t)n0 * EE;
    const __nv_bfloat16* s3 = g_Wlo + woff + (size_t)n0 * EE;

    const int lrow = tid >> 3;
    const int lch  = tid & 7;
    auto stage_load = [&](int k0, int stg) {
        uint32_t sb = sbase + (uint32_t)stg * 65536u;
        #pragma unroll
        for (int t = 0; t < 4; t++) {
            const __nv_bfloat16* sp = (t==0?s0:t==1?s1:t==2?s2:s3) + k0 + lch*8;
            uint32_t tb = sb + (uint32_t)t * 16384u;
            #pragma unroll
            for (int j = 0; j < 4; j++) {
                int row = lrow + j*32;
                CP_ASYNC16(tb + row*128 + ((lch ^ (row & 7)) << 4),
                           sp + (size_t)row * EE);
            }
        }
        CP_COMMIT();
    };

    const int l7 = lane & 7;
    uint32_t aoff[4], boff[2];
    #pragma unroll
    for (int t = 0; t < 4; t++)
        aoff[t] = (uint32_t)(m0w + t*16 + (lane & 15)) * 128u;
    #pragma unroll
    for (int p = 0; p < 2; p++)
        boff[p] = (uint32_t)(n0w + p*16 + l7 + ((lane >> 4) << 3)) * 128u;
    const int achk = lane >> 4;
    const int bchk = (lane >> 3) & 1;

    float acc[4][4][4] = {};

    stage_load(0, 0);

    #pragma unroll 1
    for (int s = 0; s < EE/64; s++) {
        CP_WAIT0();
        __syncthreads();
        if (s + 1 < EE/64) stage_load((s + 1) * 64, (s + 1) & 1);

        const uint32_t stg = sbase + (uint32_t)(s & 1) * 65536u;
        const uint32_t Ahi = stg, Alo = stg + 16384u;
        const uint32_t Bhi = stg + 32768u, Blo = stg + 49152u;

        #pragma unroll
        for (int ks = 0; ks < 4; ks++) {
            const uint32_t asw = (uint32_t)((2*ks + achk) ^ l7) << 4;
            const uint32_t bsw = (uint32_t)((2*ks + bchk) ^ l7) << 4;
            uint32_t Ah[4][4], Al[4][4], Bh[2][4], Bl[2][4];
            #pragma unroll
            for (int t = 0; t < 4; t++) {
                LDSM4(Ah[t], Ahi + aoff[t] + asw);
                LDSM4(Al[t], Alo + aoff[t] + asw);
            }
            #pragma unroll
            for (int p = 0; p < 2; p++) {
                LDSM4(Bh[p], Bhi + boff[p] + bsw);
                LDSM4(Bl[p], Blo + boff[p] + bsw);
            }
            #pragma unroll
            for (int t = 0; t < 4; t++)
                #pragma unroll
                for (int n = 0; n < 4; n++) {
                    const int p = n >> 1, q = (n & 1) * 2;
                    MMA_BF16(acc[t][n], Ah[t], Bh[p][q], Bh[p][q+1]);
                    MMA_BF16(acc[t][n], Ah[t], Bl[p][q], Bl[p][q+1]);
                    MMA_BF16(acc[t][n], Al[t], Bh[p][q], Bh[p][q+1]);
                }
        }
        __syncthreads();
    }

    // epilogue
    const int rl = lane >> 2, cl2 = (lane & 3) * 2;
    #pragma unroll
    for (int t = 0; t < 4; t++)
        #pragma unroll
        for (int n = 0; n < 4; n++) {
            const int col = n0 + n0w + n*8 + cl2;
            #pragma unroll
            for (int half = 0; half < 2; half++) {
                const int row = m0 + m0w + t*16 + rl + half*8;
                float ox = (acc[t][n][half*2+0] + bias[col+0]) * scale;
                float oy = (acc[t][n][half*2+1] + bias[col+1]) * scale;
                if (is_qkv) {
                    const int hh = col >> 6, d0 = col & 63;
                    const int bb_ = row >> 10, ss_ = row & 1023;
                    size_t idx = ((size_t)((bb_*HH + hh)*SS + ss_))*DD + d0;
                    uint32_t hi, lo;
                    splitpack(ox, oy, hi, lo);
                    *(uint32_t*)(outHi + idx) = hi;
                    *(uint32_t*)(outLo + idx) = lo;
                } else {
                    float2 o; o.x = ox; o.y = oy;
                    *(float2*)(outp + (size_t)row * EE + col) = o;
                }
            }
        }
}

// ---------------------------------------------------------------------------
// Flash attention on mma.sync bf16 (3-split). CTA = 128 Q rows x (b,h).
// 8 warps, warp = m16 x n64. K/V chunks of 64 rows, double-buffered cp.async.
// Smem: Q stage 32KB | 2 KV stages (Khi,Klo,Vhi,Vlo; 8KB each) | pk[1024].
// ---------------------------------------------------------------------------
__global__ void __launch_bounds__(256) attn_mma_kernel(
    const int* __restrict__ pos_row, const int* __restrict__ pos_col,
    const float* __restrict__ rel_table)
{
    extern __shared__ char dsm[];
    const uint32_t sbase = smem_u32(dsm);
    const uint32_t sQhi = sbase, sQlo = sbase + 16384u;
    int* pk = (int*)(dsm + 98304);

    const int tid = threadIdx.x;
    const int wid = tid >> 5, lane = tid & 31;
    const int l7 = lane & 7;
    const int rl = lane >> 2, cl2 = (lane & 3) * 2;
    const int achk = lane >> 4;
    const int bchk = (lane >> 3) & 1;

    const int q0 = blockIdx.x * 128;
    const int h = blockIdx.y, b = blockIdx.z;
    const size_t hb = (size_t)(b*HH + h) * SS * DD;

    // pos packing into smem (whole sequence for this batch)
    #pragma unroll
    for (int i = 0; i < 4; i++) {
        int s = tid + i*256;
        pk[s] = (pos_row[b*SS + s] << 5) | pos_col[b*SS + s];
    }

    // Q stage: 128 rows x 64 bf16 hi/lo (group 0)
    {
        const int half = tid >> 7, r = tid & 127;
        const __nv_bfloat16* src = (half ? g_Qlo : g_Qhi) + hb + (size_t)(q0 + r)*DD;
        uint32_t dstrow = (half ? sQlo : sQhi) + (uint32_t)r * 128u;
        #pragma unroll
        for (int ch = 0; ch < 8; ch++)
            CP_ASYNC16(dstrow + ((ch ^ (r & 7)) << 4), src + ch*8);
        CP_COMMIT();
    }

    auto kv_load = [&](int kb, int stg) {
        const int t = tid >> 6, r = tid & 63;
        const __nv_bfloat16* src =
            (t==0 ? g_Khi : t==1 ? g_Klo : t==2 ? g_Vhi : g_Vlo)
            + hb + (size_t)(kb + r)*DD;
        uint32_t dstrow = sbase + 32768u + (uint32_t)stg*32768u
                        + (uint32_t)t*8192u + (uint32_t)r*128u;
        #pragma unroll
        for (int ch = 0; ch < 8; ch++)
            CP_ASYNC16(dstrow + ((ch ^ (r & 7)) << 4), src + ch*8);
        CP_COMMIT();
    };
    kv_load(0, 0);   // group 1

    CP_WAIT1();      // Q stage ready
    __syncthreads();

    // Q fragments (resident): 4 k-steps x hi/lo
    uint32_t qh[4][4], ql[4][4];
    const uint32_t aq = (uint32_t)(wid*16 + (lane & 15)) * 128u;
    #pragma unroll
    for (int ks = 0; ks < 4; ks++) {
        uint32_t sw = (uint32_t)((2*ks + achk) ^ l7) << 4;
        LDSM4(qh[ks], sQhi + aq + sw);
        LDSM4(ql[ks], sQlo + aq + sw);
    }

    const int rq0 = pk[q0 + wid*16 + rl];
    const int rq1 = pk[q0 + wid*16 + rl + 8];
    const float tb0 = rel_table[0*HH + h];
    const float tb1 = rel_table[1*HH + h];
    const float tb2 = rel_table[2*HH + h];
    const float tb3 = rel_table[3*HH + h];

    float oacc[8][4] = {};
    float m0 = -1e30f, m1 = -1e30f, l0 = 0.f, l1 = 0.f;

    #pragma unroll 1
    for (int kt = 0; kt < SS/64; kt++) {
        CP_WAIT0();
        __syncthreads();
        if (kt + 1 < SS/64) kv_load((kt + 1) * 64, (kt + 1) & 1);

        const uint32_t st  = sbase + 32768u + (uint32_t)(kt & 1) * 32768u;
        const uint32_t Khi = st, Klo = st + 8192u;
        const uint32_t Vhi = st + 16384u, Vlo = st + 24576u;

        // S = Q K^T  (m16 x n64), fp32 accum
        float sacc[8][4] = {};
        #pragma unroll
        for (int ks = 0; ks < 4; ks++) {
            const uint32_t bsw = (uint32_t)((2*ks + bchk) ^ l7) << 4;
            #pragma unroll
            for (int p = 0; p < 4; p++) {
                const uint32_t bo =
                    (uint32_t)(p*16 + l7 + ((lane >> 4) << 3)) * 128u + bsw;
                uint32_t Bh[4], Bl[4];
                LDSM4(Bh, Khi + bo);
                LDSM4(Bl, Klo + bo);
                MMA_BF16(sacc[2*p],   qh[ks], Bh[0], Bh[1]);
                MMA_BF16(sacc[2*p],   qh[ks], Bl[0], Bl[1]);
                MMA_BF16(sacc[2*p],   ql[ks], Bh[0], Bh[1]);
                MMA_BF16(sacc[2*p+1], qh[ks], Bh[2], Bh[3]);
                MMA_BF16(sacc[2*p+1], qh[ks], Bl[2], Bl[3]);
                MMA_BF16(sacc[2*p+1], ql[ks], Bh[2], Bh[3]);
            }
        }

        // bias
        const int kb = kt * 64;
        #pragma unroll
        for (int t = 0; t < 8; t++) {
            int c0 = kb + t*8 + cl2;
            int rk0 = pk[c0], rk1 = pk[c0 + 1];
            int x;
            x = rq0 ^ rk0; sacc[t][0] += (x < 32) ? (((x & 31) == 0) ? tb3 : tb1)
                                                  : (((x & 31) == 0) ? tb2 : tb0);
            x = rq0 ^ rk1; sacc[t][1] += (x < 32) ? (((x & 31) == 0) ? tb3 : tb1)
                                                  : (((x & 31) == 0) ? tb2 : tb0);
            x = rq1 ^ rk0; sacc[t][2] += (x < 32) ? (((x & 31) == 0) ? tb3 : tb1)
                                                  : (((x & 31) == 0) ? tb2 : tb0);
            x = rq1 ^ rk1; sacc[t][3] += (x < 32) ? (((x & 31) == 0) ? tb3 : tb1)
                                                  : (((x & 31) == 0) ? tb2 : tb0);
        }

        // online softmax: rows rl (regs 0,1) and rl+8 (regs 2,3); 4 lanes/row
        float mx0 = sacc[0][0], mx1 = sacc[0][2];
        #pragma unroll
        for (int t = 0; t < 8; t++) {
            mx0 = fmaxf(mx0, fmaxf(sacc[t][0], sacc[t][1]));
            mx1 = fmaxf(mx1, fmaxf(sacc[t][2], sacc[t][3]));
        }
        mx0 = fmaxf(mx0, __shfl_xor_sync(0xffffffffu, mx0, 1));
        mx0 = fmaxf(mx0, __shfl_xor_sync(0xffffffffu, mx0, 2));
        mx1 = fmaxf(mx1, __shfl_xor_sync(0xffffffffu, mx1, 1));
        mx1 = fmaxf(mx1, __shfl_xor_sync(0xffffffffu, mx1, 2));
        float mn0 = fmaxf(m0, mx0), mn1 = fmaxf(m1, mx1);
        float sc0 = fexp(m0 - mn0), sc1 = fexp(m1 - mn1);
        m0 = mn0; m1 = mn1;
        float rs0 = 0.f, rs1 = 0.f;
        #pragma unroll
        for (int t = 0; t < 8; t++) {
            sacc[t][0] = fexp(sacc[t][0] - mn0);
            sacc[t][1] = fexp(sacc[t][1] - mn0);
            sacc[t][2] = fexp(sacc[t][2] - mn1);
            sacc[t][3] = fexp(sacc[t][3] - mn1);
            rs0 += sacc[t][0] + sacc[t][1];
            rs1 += sacc[t][2] + sacc[t][3];
        }
        rs0 += __shfl_xor_sync(0xffffffffu, rs0, 1);
        rs0 += __shfl_xor_sync(0xffffffffu, rs0, 2);
        rs1 += __shfl_xor_sync(0xffffffffu, rs1, 1);
        rs1 += __shfl_xor_sync(0xffffffffu, rs1, 2);
        l0 = l0 * sc0 + rs0;
        l1 = l1 * sc1 + rs1;
        #pragma unroll
        for (int t = 0; t < 8; t++) {
            oacc[t][0] *= sc0; oacc[t][1] *= sc0;
            oacc[t][2] *= sc1; oacc[t][3] *= sc1;
        }

        // O += P V : P fragments straight from sacc (hi/lo split)
        #pragma unroll
        for (int ks = 0; ks < 4; ks++) {
            uint32_t ph[4], pl[4];
            splitpack(sacc[2*ks][0],   sacc[2*ks][1],   ph[0], pl[0]);
            splitpack(sacc[2*ks][2],   sacc[2*ks][3],   ph[1], pl[1]);
            splitpack(sacc[2*ks+1][0], sacc[2*ks+1][1], ph[2], pl[2]);
            splitpack(sacc[2*ks+1][2], sacc[2*ks+1][3], ph[3], pl[3]);
            const uint32_t vr =
                (uint32_t)(ks*16 + l7 + (((lane >> 3) & 1) << 3)) * 128u;
            #pragma unroll
            for (int p = 0; p < 4; p++) {
                const uint32_t vsw = (uint32_t)((2*p + achk) ^ l7) << 4;
                uint32_t Vh[4], Vl[4];
                LDSM4T(Vh, Vhi + vr + vsw);
                LDSM4T(Vl, Vlo + vr + vsw);
                MMA_BF16(oacc[2*p],   ph, Vh[0], Vh[1]);
                MMA_BF16(oacc[2*p],   ph, Vl[0], Vl[1]);
                MMA_BF16(oacc[2*p],   pl, Vh[0], Vh[1]);
                MMA_BF16(oacc[2*p+1], ph, Vh[2], Vh[3]);
                MMA_BF16(oacc[2*p+1], ph, Vl[2], Vl[3]);
                MMA_BF16(oacc[2*p+1], pl, Vh[2], Vh[3]);
            }
        }
    }

    // epilogue: normalize, emit bf16 hi/lo AO at [B,S,E] (e = h*64+d)
    const float inv0 = 1.0f / l0, inv1 = 1.0f / l1;
    const int qrow0 = q0 + wid*16 + rl;
    #pragma unroll
    for (int t = 0; t < 8; t++) {
        const int e = h*64 + t*8 + cl2;
        size_t i0 = (size_t)(b*SS + qrow0) * EE + e;
        size_t i1 = (size_t)(b*SS + qrow0 + 8) * EE + e;
        uint32_t hi, lo;
        splitpack(oacc[t][0] * inv0, oacc[t][1] * inv0, hi, lo);
        *(uint32_t*)(g_AOhi + i0) = hi;
        *(uint32_t*)(g_AOlo + i0) = lo;
        splitpack(oacc[t][2] * inv1, oacc[t][3] * inv1, hi, lo);
        *(uint32_t*)(g_AOhi + i1) = hi;
        *(uint32_t*)(g_AOlo + i1) = lo;
    }
}

// ---------------------------------------------------------------------------
extern "C" void kernel_launch(void* const* d_in, const int* in_sizes, int n_in,
                              void* d_out, int out_size) {
    const float* X  = (const float*)d_in[0];
    const int*   pr = (const int*)  d_in[1];
    const int*   pc = (const int*)  d_in[2];
    const float* qw = (const float*)d_in[3];
    const float* qb = (const float*)d_in[4];
    const float* kw = (const float*)d_in[5];
    const float* kb = (const float*)d_in[6];
    const float* vw = (const float*)d_in[7];
    const float* vb = (const float*)d_in[8];
    const float* ow = (const float*)d_in[9];
    const float* ob = (const float*)d_in[10];
    const float* rt = (const float*)d_in[11];
    float* out = (float*)d_out;

    const int DSMEM_G = 2 * 65536;
    cudaFuncSetAttribute(gemm_mma_kernel,
                         cudaFuncAttributeMaxDynamicSharedMemorySize, DSMEM_G);
    const int DSMEM_A = 32768 + 2*32768 + 4096;   // 102400
    cudaFuncSetAttribute(attn_mma_kernel,
                         cudaFuncAttributeMaxDynamicSharedMemorySize, DSMEM_A);

    splitX_kernel<<<MT*EE/1024, 256>>>(X);
    splitW_kernel<<<EE*EE/1024, 256>>>(qw, 0);
    splitW_kernel<<<EE*EE/1024, 256>>>(kw, 1);
    splitW_kernel<<<EE*EE/1024, 256>>>(vw, 2);
    splitW_kernel<<<EE*EE/1024, 256>>>(ow, 3);

    dim3 g1(EE/128, MT/128, 3);
    gemm_mma_kernel<<<g1, 256, DSMEM_G>>>(qb, kb, vb, nullptr, 0, 1);

    dim3 g2(SS/128, HH, BB);
    attn_mma_kernel<<<g2, 256, DSMEM_A>>>(pr, pc, rt);

    dim3 g3(EE/128, MT/128, 1);
    gemm_mma_kernel<<<g3, 256, DSMEM_G>>>(ob, ob, ob, out, 3, 0);
}

// round 6
// speedup vs baseline: 3.0999x; 1.0971x over previous
#include <cuda_runtime.h>
#include <cuda_bf16.h>
#include <cstdint>
#include <math.h>

#define BB 4
#define SS 1024
#define EE 768
#define HH 12
#define DD 64
#define MT (BB*SS)
#define SCALING 0.125f

// ---------------- device scratch (allocation-free rule) ----------------
__device__ __nv_bfloat16 g_Qhi[BB*HH*SS*DD], g_Qlo[BB*HH*SS*DD];
__device__ __nv_bfloat16 g_Khi[BB*HH*SS*DD], g_Klo[BB*HH*SS*DD];
__device__ __nv_bfloat16 g_Vhi[BB*HH*SS*DD], g_Vlo[BB*HH*SS*DD];
__device__ __nv_bfloat16 g_Xhi[MT*EE],  g_Xlo[MT*EE];
__device__ __nv_bfloat16 g_Whi[4*EE*EE], g_Wlo[4*EE*EE];
__device__ __nv_bfloat16 g_AOhi[MT*EE], g_AOlo[MT*EE];

__device__ __forceinline__ uint32_t smem_u32(const void* p) {
    uint32_t a;
    asm("{ .reg .u64 t; cvta.to.shared.u64 t, %1; cvt.u32.u64 %0, t; }"
        : "=r"(a) : "l"(p));
    return a;
}

#define LDSM4(r, addr) \
    asm volatile("ldmatrix.sync.aligned.m8n8.x4.shared.b16 {%0,%1,%2,%3}, [%4];" \
        : "=r"((r)[0]), "=r"((r)[1]), "=r"((r)[2]), "=r"((r)[3]) : "r"(addr))
#define LDSM4T(r, addr) \
    asm volatile("ldmatrix.sync.aligned.m8n8.x4.trans.shared.b16 {%0,%1,%2,%3}, [%4];" \
        : "=r"((r)[0]), "=r"((r)[1]), "=r"((r)[2]), "=r"((r)[3]) : "r"(addr))

#define MMA_BF16(d, a, b0v, b1v) \
    asm volatile("mma.sync.aligned.m16n8k16.row.col.f32.bf16.bf16.f32 " \
        "{%0,%1,%2,%3}, {%4,%5,%6,%7}, {%8,%9}, {%0,%1,%2,%3};" \
        : "+f"((d)[0]), "+f"((d)[1]), "+f"((d)[2]), "+f"((d)[3]) \
        : "r"((a)[0]), "r"((a)[1]), "r"((a)[2]), "r"((a)[3]), "r"(b0v), "r"(b1v))

#define CP_ASYNC16(smem, gmem) \
    asm volatile("cp.async.cg.shared.global [%0], [%1], 16;" :: "r"(smem), "l"(gmem))
#define CP_COMMIT()  asm volatile("cp.async.commit_group;" ::: "memory")
#define CP_WAIT0()   asm volatile("cp.async.wait_group 0;" ::: "memory")
#define CP_WAIT1()   asm volatile("cp.async.wait_group 1;" ::: "memory")

// pack 2 fp32 -> bf16x2 hi + bf16x2 lo (3-split residual), cvt.bf16x2 fast path
__device__ __forceinline__ void splitpack(float x, float y, uint32_t& hi, uint32_t& lo) {
    asm("cvt.rn.bf16x2.f32 %0, %1, %2;" : "=r"(hi) : "f"(y), "f"(x));
    float hx = __uint_as_float(hi << 16);
    float hy = __uint_as_float(hi & 0xffff0000u);
    float lx = x - hx, ly = y - hy;
    asm("cvt.rn.bf16x2.f32 %0, %1, %2;" : "=r"(lo) : "f"(ly), "f"(lx));
}

// ---------------------------------------------------------------------------
// merged fp32 -> (bf16 hi, lo) split: blocks [0,3072) = X, then 4x576 = W slots
// ---------------------------------------------------------------------------
__global__ void __launch_bounds__(256) split_all_kernel(
    const float* __restrict__ X,
    const float* __restrict__ qw, const float* __restrict__ kw,
    const float* __restrict__ vw, const float* __restrict__ ow)
{
    const int bid = blockIdx.x;
    const float* src;
    __nv_bfloat16 *dhi, *dlo;
    size_t off;
    if (bid < 3072) {
        src = X; dhi = g_Xhi; dlo = g_Xlo;
        off = (size_t)bid * 1024;
    } else {
        int r = bid - 3072;
        int slot = r / 576, rb = r % 576;
        src = (slot == 0) ? qw : (slot == 1) ? kw : (slot == 2) ? vw : ow;
        dhi = g_Whi + (size_t)slot * EE * EE;
        dlo = g_Wlo + (size_t)slot * EE * EE;
        off = (size_t)rb * 1024;
    }
    size_t i = off + threadIdx.x * 4;
    float4 v = *(const float4*)(src + i);
    float xs[4] = {v.x, v.y, v.z, v.w};
    #pragma unroll
    for (int j = 0; j < 4; j++) {
        __nv_bfloat16 hv = __float2bfloat16(xs[j]);
        dhi[i+j] = hv;
        dlo[i+j] = __float2bfloat16(xs[j] - __bfloat162float(hv));
    }
}

// ---------------------------------------------------------------------------
// HMMA GEMM: D = A(M,K) @ W(N,K)^T via 3x bf16-split mma.sync, fp32 accum.
// CTA 128x128, 8 warps (2x4), warp tile 64x32, BK=32, double-buffered cp.async.
// Stage = 4 tiles (Ahi,Alo,Bhi,Blo) of [128 x 32 bf16] = 32KB; 2 CTAs/SM.
// Rows are 64B; swizzle: chunk16B ^= ((row>>1)&3).
// ---------------------------------------------------------------------------
__global__ void __launch_bounds__(256, 2) gemm_mma_kernel(
    const float* __restrict__ b0p, const float* __restrict__ b1p,
    const float* __restrict__ b2p, float* __restrict__ outp,
    int wslot0, int is_qkv)
{
    extern __shared__ char dsm[];
    const uint32_t sbase = smem_u32(dsm);

    const int tid = threadIdx.x;
    const int wid = tid >> 5, lane = tid & 31;
    const int warp_m = wid & 1, warp_n = wid >> 1;
    const int m0w = warp_m * 64, n0w = warp_n * 32;

    const int z = is_qkv ? blockIdx.z : 0;
    const size_t woff = (size_t)(wslot0 + z) * EE * EE;
    const float* bias = (z == 0) ? b0p : (z == 1) ? b1p : b2p;
    const float scale = (is_qkv && z == 0) ? SCALING : 1.0f;
    __nv_bfloat16* outHi = (z == 0) ? g_Qhi : (z == 1) ? g_Khi : g_Vhi;
    __nv_bfloat16* outLo = (z == 0) ? g_Qlo : (z == 1) ? g_Klo : g_Vlo;

    const int n0 = blockIdx.x * 128;
    const int m0 = blockIdx.y * 128;

    const __nv_bfloat16* s0 = (is_qkv ? g_Xhi : g_AOhi) + (size_t)m0 * EE;
    const __nv_bfloat16* s1 = (is_qkv ? g_Xlo : g_AOlo) + (size_t)m0 * EE;
    const __nv_bfloat16* s2 = g_Whi + woff + (size_t)n0 * EE;
    const __nv_bfloat16* s3 = g_Wlo + woff + (size_t)n0 * EE;

    // loader: per tile 128 rows x 4 chunks(16B) = 512; 256 thr -> 2 each
    const int lrow = tid >> 2;           // 0..63 base row
    const int lch  = tid & 3;            // chunk 0..3
    auto stage_load = [&](int k0, int stg) {
        uint32_t sb = sbase + (uint32_t)stg * 32768u;
        #pragma unroll
        for (int t = 0; t < 4; t++) {
            const __nv_bfloat16* sp = (t==0?s0:t==1?s1:t==2?s2:s3) + k0 + lch*8;
            uint32_t tb = sb + (uint32_t)t * 8192u;
            #pragma unroll
            for (int j = 0; j < 2; j++) {
                int row = lrow + j*64;
                CP_ASYNC16(tb + row*64 + ((lch ^ ((row >> 1) & 3)) << 4),
                           sp + (size_t)row * EE);
            }
        }
        CP_COMMIT();
    };

    const int l7 = lane & 7;
    const int arow_sw = (lane >> 1) & 3;                 // ((lane&15)>>1)&3
    const int brow7 = l7 + ((lane >> 4) << 3);           // 0..15
    const int brow_sw = (brow7 >> 1) & 3;
    uint32_t aoff[4], boff[2];
    #pragma unroll
    for (int t = 0; t < 4; t++)
        aoff[t] = (uint32_t)(m0w + t*16 + (lane & 15)) * 64u;
    #pragma unroll
    for (int p = 0; p < 2; p++)
        boff[p] = (uint32_t)(n0w + p*16 + brow7) * 64u;
    const int achk = lane >> 4;
    const int bchk = (lane >> 3) & 1;

    float acc[4][4][4] = {};

    stage_load(0, 0);

    #pragma unroll 1
    for (int s = 0; s < EE/32; s++) {
        CP_WAIT0();
        __syncthreads();
        if (s + 1 < EE/32) stage_load((s + 1) * 32, (s + 1) & 1);

        const uint32_t stg = sbase + (uint32_t)(s & 1) * 32768u;
        const uint32_t Ahi = stg, Alo = stg + 8192u;
        const uint32_t Bhi = stg + 16384u, Blo = stg + 24576u;

        #pragma unroll
        for (int ks = 0; ks < 2; ks++) {
            const uint32_t asw = (uint32_t)((2*ks + achk) ^ arow_sw) << 4;
            const uint32_t bsw = (uint32_t)((2*ks + bchk) ^ brow_sw) << 4;
            uint32_t Bh[2][4], Bl[2][4];
            #pragma unroll
            for (int p = 0; p < 2; p++) {
                LDSM4(Bh[p], Bhi + boff[p] + bsw);
                LDSM4(Bl[p], Blo + boff[p] + bsw);
            }
            #pragma unroll
            for (int t = 0; t < 4; t++) {
                uint32_t Ah[4], Al[4];
                LDSM4(Ah, Ahi + aoff[t] + asw);
                LDSM4(Al, Alo + aoff[t] + asw);
                #pragma unroll
                for (int n = 0; n < 4; n++) {
                    const int p = n >> 1, q = (n & 1) * 2;
                    MMA_BF16(acc[t][n], Ah, Bh[p][q], Bh[p][q+1]);
                    MMA_BF16(acc[t][n], Ah, Bl[p][q], Bl[p][q+1]);
                    MMA_BF16(acc[t][n], Al, Bh[p][q], Bh[p][q+1]);
                }
            }
        }
        __syncthreads();
    }

    // epilogue
    const int rl = lane >> 2, cl2 = (lane & 3) * 2;
    #pragma unroll
    for (int t = 0; t < 4; t++)
        #pragma unroll
        for (int n = 0; n < 4; n++) {
            const int col = n0 + n0w + n*8 + cl2;
            #pragma unroll
            for (int half = 0; half < 2; half++) {
                const int row = m0 + m0w + t*16 + rl + half*8;
                float ox = (acc[t][n][half*2+0] + bias[col+0]) * scale;
                float oy = (acc[t][n][half*2+1] + bias[col+1]) * scale;
                if (is_qkv) {
                    const int hh = col >> 6, d0 = col & 63;
                    const int bb_ = row >> 10, ss_ = row & 1023;
                    size_t idx = ((size_t)((bb_*HH + hh)*SS + ss_))*DD + d0;
                    uint32_t hi, lo;
                    splitpack(ox, oy, hi, lo);
                    *(uint32_t*)(outHi + idx) = hi;
                    *(uint32_t*)(outLo + idx) = lo;
                } else {
                    float2 o; o.x = ox; o.y = oy;
                    *(float2*)(outp + (size_t)row * EE + col) = o;
                }
            }
        }
}

// ---------------------------------------------------------------------------
// Flash attention on mma.sync bf16 (3-split). CTA = 128 Q rows x (b,h).
// 8 warps, warp = m16 x n64. K/V chunks of 64 rows, double-buffered cp.async.
// Smem: Q stage 32KB | 2 KV stages (Khi,Klo,Vhi,Vlo; 8KB each) | pk[1024].
// ---------------------------------------------------------------------------
__global__ void __launch_bounds__(256) attn_mma_kernel(
    const int* __restrict__ pos_row, const int* __restrict__ pos_col,
    const float* __restrict__ rel_table)
{
    extern __shared__ char dsm[];
    const uint32_t sbase = smem_u32(dsm);
    const uint32_t sQhi = sbase, sQlo = sbase + 16384u;
    int* pk = (int*)(dsm + 98304);

    const int tid = threadIdx.x;
    const int wid = tid >> 5, lane = tid & 31;
    const int l7 = lane & 7;
    const int rl = lane >> 2, cl2 = (lane & 3) * 2;
    const int achk = lane >> 4;
    const int bchk = (lane >> 3) & 1;

    const int q0 = blockIdx.x * 128;
    const int h = blockIdx.y, b = blockIdx.z;
    const size_t hb = (size_t)(b*HH + h) * SS * DD;

    #pragma unroll
    for (int i = 0; i < 4; i++) {
        int s = tid + i*256;
        pk[s] = (pos_row[b*SS + s] << 5) | pos_col[b*SS + s];
    }

    // Q stage: 128 rows x 64 bf16 hi/lo (group 0)
    {
        const int half = tid >> 7, r = tid & 127;
        const __nv_bfloat16* src = (half ? g_Qlo : g_Qhi) + hb + (size_t)(q0 + r)*DD;
        uint32_t dstrow = (half ? sQlo : sQhi) + (uint32_t)r * 128u;
        #pragma unroll
        for (int ch = 0; ch < 8; ch++)
            CP_ASYNC16(dstrow + ((ch ^ (r & 7)) << 4), src + ch*8);
        CP_COMMIT();
    }

    auto kv_load = [&](int kb, int stg) {
        const int t = tid >> 6, r = tid & 63;
        const __nv_bfloat16* src =
            (t==0 ? g_Khi : t==1 ? g_Klo : t==2 ? g_Vhi : g_Vlo)
            + hb + (size_t)(kb + r)*DD;
        uint32_t dstrow = sbase + 32768u + (uint32_t)stg*32768u
                        + (uint32_t)t*8192u + (uint32_t)r*128u;
        #pragma unroll
        for (int ch = 0; ch < 8; ch++)
            CP_ASYNC16(dstrow + ((ch ^ (r & 7)) << 4), src + ch*8);
        CP_COMMIT();
    };
    kv_load(0, 0);

    CP_WAIT1();
    __syncthreads();

    uint32_t qh[4][4], ql[4][4];
    const uint32_t aq = (uint32_t)(wid*16 + (lane & 15)) * 128u;
    #pragma unroll
    for (int ks = 0; ks < 4; ks++) {
        uint32_t sw = (uint32_t)((2*ks + achk) ^ l7) << 4;
        LDSM4(qh[ks], sQhi + aq + sw);
        LDSM4(ql[ks], sQlo + aq + sw);
    }

    const int rq0 = pk[q0 + wid*16 + rl];
    const int rq1 = pk[q0 + wid*16 + rl + 8];
    const float tb0 = rel_table[0*HH + h];
    const float tb1 = rel_table[1*HH + h];
    const float tb2 = rel_table[2*HH + h];
    const float tb3 = rel_table[3*HH + h];

    float oacc[8][4] = {};
    float m0 = -1e30f, m1 = -1e30f, l0 = 0.f, l1 = 0.f;

    #pragma unroll 1
    for (int kt = 0; kt < SS/64; kt++) {
        CP_WAIT0();
        __syncthreads();
        if (kt + 1 < SS/64) kv_load((kt + 1) * 64, (kt + 1) & 1);

        const uint32_t st  = sbase + 32768u + (uint32_t)(kt & 1) * 32768u;
        const uint32_t Khi = st, Klo = st + 8192u;
        const uint32_t Vhi = st + 16384u, Vlo = st + 24576u;

        // S = Q K^T  (m16 x n64), fp32 accum
        float sacc[8][4] = {};
        #pragma unroll
        for (int ks = 0; ks < 4; ks++) {
            const uint32_t bsw = (uint32_t)((2*ks + bchk) ^ l7) << 4;
            #pragma unroll
            for (int p = 0; p < 4; p++) {
                const uint32_t bo =
                    (uint32_t)(p*16 + l7 + ((lane >> 4) << 3)) * 128u + bsw;
                uint32_t Bh[4], Bl[4];
                LDSM4(Bh, Khi + bo);
                LDSM4(Bl, Klo + bo);
                MMA_BF16(sacc[2*p],   qh[ks], Bh[0], Bh[1]);
                MMA_BF16(sacc[2*p],   qh[ks], Bl[0], Bl[1]);
                MMA_BF16(sacc[2*p],   ql[ks], Bh[0], Bh[1]);
                MMA_BF16(sacc[2*p+1], qh[ks], Bh[2], Bh[3]);
                MMA_BF16(sacc[2*p+1], qh[ks], Bl[2], Bl[3]);
                MMA_BF16(sacc[2*p+1], ql[ks], Bh[2], Bh[3]);
            }
        }

        // bias
        const int kb = kt * 64;
        #pragma unroll
        for (int t = 0; t < 8; t++) {
            int c0 = kb + t*8 + cl2;
            int rk0 = pk[c0], rk1 = pk[c0 + 1];
            int x;
            x = rq0 ^ rk0; sacc[t][0] += (x < 32) ? (((x & 31) == 0) ? tb3 : tb1)
                                                  : (((x & 31) == 0) ? tb2 : tb0);
            x = rq0 ^ rk1; sacc[t][1] += (x < 32) ? (((x & 31) == 0) ? tb3 : tb1)
                                                  : (((x & 31) == 0) ? tb2 : tb0);
            x = rq1 ^ rk0; sacc[t][2] += (x < 32) ? (((x & 31) == 0) ? tb3 : tb1)
                                                  : (((x & 31) == 0) ? tb2 : tb0);
            x = rq1 ^ rk1; sacc[t][3] += (x < 32) ? (((x & 31) == 0) ? tb3 : tb1)
                                                  : (((x & 31) == 0) ? tb2 : tb0);
        }

        // online softmax (MUFU exp; 4 lanes/row)
        float mx0 = sacc[0][0], mx1 = sacc[0][2];
        #pragma unroll
        for (int t = 0; t < 8; t++) {
            mx0 = fmaxf(mx0, fmaxf(sacc[t][0], sacc[t][1]));
            mx1 = fmaxf(mx1, fmaxf(sacc[t][2], sacc[t][3]));
        }
        mx0 = fmaxf(mx0, __shfl_xor_sync(0xffffffffu, mx0, 1));
        mx0 = fmaxf(mx0, __shfl_xor_sync(0xffffffffu, mx0, 2));
        mx1 = fmaxf(mx1, __shfl_xor_sync(0xffffffffu, mx1, 1));
        mx1 = fmaxf(mx1, __shfl_xor_sync(0xffffffffu, mx1, 2));
        float mn0 = fmaxf(m0, mx0), mn1 = fmaxf(m1, mx1);
        float sc0 = __expf(m0 - mn0), sc1 = __expf(m1 - mn1);
        m0 = mn0; m1 = mn1;
        float rs0 = 0.f, rs1 = 0.f;
        #pragma unroll
        for (int t = 0; t < 8; t++) {
            sacc[t][0] = __expf(sacc[t][0] - mn0);
            sacc[t][1] = __expf(sacc[t][1] - mn0);
            sacc[t][2] = __expf(sacc[t][2] - mn1);
            sacc[t][3] = __expf(sacc[t][3] - mn1);
            rs0 += sacc[t][0] + sacc[t][1];
            rs1 += sacc[t][2] + sacc[t][3];
        }
        rs0 += __shfl_xor_sync(0xffffffffu, rs0, 1);
        rs0 += __shfl_xor_sync(0xffffffffu, rs0, 2);
        rs1 += __shfl_xor_sync(0xffffffffu, rs1, 1);
        rs1 += __shfl_xor_sync(0xffffffffu, rs1, 2);
        l0 = l0 * sc0 + rs0;
        l1 = l1 * sc1 + rs1;
        #pragma unroll
        for (int t = 0; t < 8; t++) {
            oacc[t][0] *= sc0; oacc[t][1] *= sc0;
            oacc[t][2] *= sc1; oacc[t][3] *= sc1;
        }

        // O += P V : P fragments straight from sacc (hi/lo split)
        #pragma unroll
        for (int ks = 0; ks < 4; ks++) {
            uint32_t ph[4], pl[4];
            splitpack(sacc[2*ks][0],   sacc[2*ks][1],   ph[0], pl[0]);
            splitpack(sacc[2*ks][2],   sacc[2*ks][3],   ph[1], pl[1]);
            splitpack(sacc[2*ks+1][0], sacc[2*ks+1][1], ph[2], pl[2]);
            splitpack(sacc[2*ks+1][2], sacc[2*ks+1][3], ph[3], pl[3]);
            const uint32_t vr =
                (uint32_t)(ks*16 + l7 + (((lane >> 3) & 1) << 3)) * 128u;
            #pragma unroll
            for (int p = 0; p < 4; p++) {
                const uint32_t vsw = (uint32_t)((2*p + achk) ^ l7) << 4;
                uint32_t Vh[4], Vl[4];
                LDSM4T(Vh, Vhi + vr + vsw);
                LDSM4T(Vl, Vlo + vr + vsw);
                MMA_BF16(oacc[2*p],   ph, Vh[0], Vh[1]);
                MMA_BF16(oacc[2*p],   ph, Vl[0], Vl[1]);
                MMA_BF16(oacc[2*p],   pl, Vh[0], Vh[1]);
                MMA_BF16(oacc[2*p+1], ph, Vh[2], Vh[3]);
                MMA_BF16(oacc[2*p+1], ph, Vl[2], Vl[3]);
                MMA_BF16(oacc[2*p+1], pl, Vh[2], Vh[3]);
            }
        }
    }

    // epilogue: normalize, emit bf16 hi/lo AO at [B,S,E] (e = h*64+d)
    const float inv0 = 1.0f / l0, inv1 = 1.0f / l1;
    const int qrow0 = q0 + wid*16 + rl;
    #pragma unroll
    for (int t = 0; t < 8; t++) {
        const int e = h*64 + t*8 + cl2;
        size_t i0 = (size_t)(b*SS + qrow0) * EE + e;
        size_t i1 = (size_t)(b*SS + qrow0 + 8) * EE + e;
        uint32_t hi, lo;
        splitpack(oacc[t][0] * inv0, oacc[t][1] * inv0, hi, lo);
        *(uint32_t*)(g_AOhi + i0) = hi;
        *(uint32_t*)(g_AOlo + i0) = lo;
        splitpack(oacc[t][2] * inv1, oacc[t][3] * inv1, hi, lo);
        *(uint32_t*)(g_AOhi + i1) = hi;
        *(uint32_t*)(g_AOlo + i1) = lo;
    }
}

// ---------------------------------------------------------------------------
extern "C" void kernel_launch(void* const* d_in, const int* in_sizes, int n_in,
                              void* d_out, int out_size) {
    const float* X  = (const float*)d_in[0];
    const int*   pr = (const int*)  d_in[1];
    const int*   pc = (const int*)  d_in[2];
    const float* qw = (const float*)d_in[3];
    const float* qb = (const float*)d_in[4];
    const float* kw = (const float*)d_in[5];
    const float* kb = (const float*)d_in[6];
    const float* vw = (const float*)d_in[7];
    const float* vb = (const float*)d_in[8];
    const float* ow = (const float*)d_in[9];
    const float* ob = (const float*)d_in[10];
    const float* rt = (const float*)d_in[11];
    float* out = (float*)d_out;

    const int DSMEM_G = 2 * 32768;
    cudaFuncSetAttribute(gemm_mma_kernel,
                         cudaFuncAttributeMaxDynamicSharedMemorySize, DSMEM_G);
    const int DSMEM_A = 32768 + 2*32768 + 4096;   // 102400
    cudaFuncSetAttribute(attn_mma_kernel,
                         cudaFuncAttributeMaxDynamicSharedMemorySize, DSMEM_A);

    split_all_kernel<<<3072 + 4*576, 256>>>(X, qw, kw, vw, ow);

    dim3 g1(EE/128, MT/128, 3);
    gemm_mma_kernel<<<g1, 256, DSMEM_G>>>(qb, kb, vb, nullptr, 0, 1);

    dim3 g2(SS/128, HH, BB);
    attn_mma_kernel<<<g2, 256, DSMEM_A>>>(pr, pc, rt);

    dim3 g3(EE/128, MT/128, 1);
    gemm_mma_kernel<<<g3, 256, DSMEM_G>>>(ob, ob, ob, out, 3, 0);
}

// round 7
// speedup vs baseline: 3.2649x; 1.0532x over previous
#include <cuda_runtime.h>
#include <cuda_bf16.h>
#include <cstdint>
#include <math.h>

#define BB 4
#define SS 1024
#define EE 768
#define HH 12
#define DD 64
#define MT (BB*SS)
#define SCALING 0.125f

// ---------------- device scratch (allocation-free rule) ----------------
__device__ __nv_bfloat16 g_Qhi[BB*HH*SS*DD], g_Qlo[BB*HH*SS*DD];
__device__ __nv_bfloat16 g_Khi[BB*HH*SS*DD], g_Klo[BB*HH*SS*DD];
__device__ __nv_bfloat16 g_Vhi[BB*HH*SS*DD], g_Vlo[BB*HH*SS*DD];
__device__ __nv_bfloat16 g_Xhi[MT*EE],  g_Xlo[MT*EE];
__device__ __nv_bfloat16 g_Whi[4*EE*EE], g_Wlo[4*EE*EE];
__device__ __nv_bfloat16 g_AOhi[MT*EE], g_AOlo[MT*EE];

__device__ __forceinline__ uint32_t smem_u32(const void* p) {
    uint32_t a;
    asm("{ .reg .u64 t; cvta.to.shared.u64 t, %1; cvt.u32.u64 %0, t; }"
        : "=r"(a) : "l"(p));
    return a;
}

#define LDSM4(r, addr) \
    asm volatile("ldmatrix.sync.aligned.m8n8.x4.shared.b16 {%0,%1,%2,%3}, [%4];" \
        : "=r"((r)[0]), "=r"((r)[1]), "=r"((r)[2]), "=r"((r)[3]) : "r"(addr))
#define LDSM4T(r, addr) \
    asm volatile("ldmatrix.sync.aligned.m8n8.x4.trans.shared.b16 {%0,%1,%2,%3}, [%4];" \
        : "=r"((r)[0]), "=r"((r)[1]), "=r"((r)[2]), "=r"((r)[3]) : "r"(addr))

#define MMA_BF16(d, a, b0v, b1v) \
    asm volatile("mma.sync.aligned.m16n8k16.row.col.f32.bf16.bf16.f32 " \
        "{%0,%1,%2,%3}, {%4,%5,%6,%7}, {%8,%9}, {%0,%1,%2,%3};" \
        : "+f"((d)[0]), "+f"((d)[1]), "+f"((d)[2]), "+f"((d)[3]) \
        : "r"((a)[0]), "r"((a)[1]), "r"((a)[2]), "r"((a)[3]), "r"(b0v), "r"(b1v))

#define CP_ASYNC16(smem, gmem) \
    asm volatile("cp.async.cg.shared.global [%0], [%1], 16;" :: "r"(smem), "l"(gmem))
#define CP_COMMIT()  asm volatile("cp.async.commit_group;" ::: "memory")
#define CP_WAIT0()   asm volatile("cp.async.wait_group 0;" ::: "memory")
#define CP_WAIT1()   asm volatile("cp.async.wait_group 1;" ::: "memory")

// pack 2 fp32 -> bf16x2 hi + bf16x2 lo (3-split residual), cvt.bf16x2 fast path
__device__ __forceinline__ void splitpack(float x, float y, uint32_t& hi, uint32_t& lo) {
    asm("cvt.rn.bf16x2.f32 %0, %1, %2;" : "=r"(hi) : "f"(y), "f"(x));
    float hx = __uint_as_float(hi << 16);
    float hy = __uint_as_float(hi & 0xffff0000u);
    float lx = x - hx, ly = y - hy;
    asm("cvt.rn.bf16x2.f32 %0, %1, %2;" : "=r"(lo) : "f"(ly), "f"(lx));
}

// ---------------------------------------------------------------------------
// merged fp32 -> (bf16 hi, lo) split: blocks [0,3072) = X, then 4x576 = W slots
// ---------------------------------------------------------------------------
__global__ void __launch_bounds__(256) split_all_kernel(
    const float* __restrict__ X,
    const float* __restrict__ qw, const float* __restrict__ kw,
    const float* __restrict__ vw, const float* __restrict__ ow)
{
    const int bid = blockIdx.x;
    const float* src;
    __nv_bfloat16 *dhi, *dlo;
    size_t off;
    if (bid < 3072) {
        src = X; dhi = g_Xhi; dlo = g_Xlo;
        off = (size_t)bid * 1024;
    } else {
        int r = bid - 3072;
        int slot = r / 576, rb = r % 576;
        src = (slot == 0) ? qw : (slot == 1) ? kw : (slot == 2) ? vw : ow;
        dhi = g_Whi + (size_t)slot * EE * EE;
        dlo = g_Wlo + (size_t)slot * EE * EE;
        off = (size_t)rb * 1024;
    }
    size_t i = off + threadIdx.x * 4;
    float4 v = *(const float4*)(src + i);
    float xs[4] = {v.x, v.y, v.z, v.w};
    #pragma unroll
    for (int j = 0; j < 4; j++) {
        __nv_bfloat16 hv = __float2bfloat16(xs[j]);
        dhi[i+j] = hv;
        dlo[i+j] = __float2bfloat16(xs[j] - __bfloat162float(hv));
    }
}

// ---------------------------------------------------------------------------
// HMMA GEMM: D = A(M,K) @ W(N,K)^T via 3x bf16-split mma.sync, fp32 accum.
// CTA 128x128, 8 warps (2x4), warp tile 64x32, BK=32, 3-stage cp.async
// pipeline (wait_group 1 slack), ONE __syncthreads per stage. 2 CTAs/SM.
// Rows are 64B; swizzle: chunk16B ^= ((row>>1)&3).
// ---------------------------------------------------------------------------
#define NS (EE/32)   // 24 K-stages
__global__ void __launch_bounds__(256, 2) gemm_mma_kernel(
    const float* __restrict__ b0p, const float* __restrict__ b1p,
    const float* __restrict__ b2p, float* __restrict__ outp,
    int wslot0, int is_qkv)
{
    extern __shared__ char dsm[];
    const uint32_t sbase = smem_u32(dsm);

    const int tid = threadIdx.x;
    const int wid = tid >> 5, lane = tid & 31;
    const int warp_m = wid & 1, warp_n = wid >> 1;
    const int m0w = warp_m * 64, n0w = warp_n * 32;

    const int z = is_qkv ? blockIdx.z : 0;
    const size_t woff = (size_t)(wslot0 + z) * EE * EE;
    const float* bias = (z == 0) ? b0p : (z == 1) ? b1p : b2p;
    const float scale = (is_qkv && z == 0) ? SCALING : 1.0f;
    __nv_bfloat16* outHi = (z == 0) ? g_Qhi : (z == 1) ? g_Khi : g_Vhi;
    __nv_bfloat16* outLo = (z == 0) ? g_Qlo : (z == 1) ? g_Klo : g_Vlo;

    const int n0 = blockIdx.x * 128;
    const int m0 = blockIdx.y * 128;

    const __nv_bfloat16* s0 = (is_qkv ? g_Xhi : g_AOhi) + (size_t)m0 * EE;
    const __nv_bfloat16* s1 = (is_qkv ? g_Xlo : g_AOlo) + (size_t)m0 * EE;
    const __nv_bfloat16* s2 = g_Whi + woff + (size_t)n0 * EE;
    const __nv_bfloat16* s3 = g_Wlo + woff + (size_t)n0 * EE;

    // loader: per tile 128 rows x 4 chunks(16B) = 512; 256 thr -> 2 each
    const int lrow = tid >> 2;           // 0..63 base row
    const int lch  = tid & 3;            // chunk 0..3
    auto stage_load = [&](int k0, int stg) {
        uint32_t sb = sbase + (uint32_t)stg * 32768u;
        #pragma unroll
        for (int t = 0; t < 4; t++) {
            const __nv_bfloat16* sp = (t==0?s0:t==1?s1:t==2?s2:s3) + k0 + lch*8;
            uint32_t tb = sb + (uint32_t)t * 8192u;
            #pragma unroll
            for (int j = 0; j < 2; j++) {
                int row = lrow + j*64;
                CP_ASYNC16(tb + row*64 + ((lch ^ ((row >> 1) & 3)) << 4),
                           sp + (size_t)row * EE);
            }
        }
        CP_COMMIT();
    };

    const int l7 = lane & 7;
    const int arow_sw = (lane >> 1) & 3;
    const int brow7 = l7 + ((lane >> 4) << 3);
    const int brow_sw = (brow7 >> 1) & 3;
    uint32_t aoff[4], boff[2];
    #pragma unroll
    for (int t = 0; t < 4; t++)
        aoff[t] = (uint32_t)(m0w + t*16 + (lane & 15)) * 64u;
    #pragma unroll
    for (int p = 0; p < 2; p++)
        boff[p] = (uint32_t)(n0w + p*16 + brow7) * 64u;
    const int achk = lane >> 4;
    const int bchk = (lane >> 3) & 1;

    float acc[4][4][4] = {};

    stage_load(0, 0);
    stage_load(32, 1);

    #pragma unroll 1
    for (int s = 0; s < NS; s++) {
        if (s == NS - 1) { CP_WAIT0(); } else { CP_WAIT1(); }
        __syncthreads();
        if (s + 2 < NS) stage_load((s + 2) * 32, (s + 2) % 3);

        const uint32_t stg = sbase + (uint32_t)(s % 3) * 32768u;
        const uint32_t Ahi = stg, Alo = stg + 8192u;
        const uint32_t Bhi = stg + 16384u, Blo = stg + 24576u;

        #pragma unroll
        for (int ks = 0; ks < 2; ks++) {
            const uint32_t asw = (uint32_t)((2*ks + achk) ^ arow_sw) << 4;
            const uint32_t bsw = (uint32_t)((2*ks + bchk) ^ brow_sw) << 4;
            uint32_t Bh[2][4], Bl[2][4];
            #pragma unroll
            for (int p = 0; p < 2; p++) {
                LDSM4(Bh[p], Bhi + boff[p] + bsw);
                LDSM4(Bl[p], Blo + boff[p] + bsw);
            }
            #pragma unroll
            for (int t = 0; t < 4; t++) {
                uint32_t Ah[4], Al[4];
                LDSM4(Ah, Ahi + aoff[t] + asw);
                LDSM4(Al, Alo + aoff[t] + asw);
                #pragma unroll
                for (int n = 0; n < 4; n++) {
                    const int p = n >> 1, q = (n & 1) * 2;
                    MMA_BF16(acc[t][n], Ah, Bh[p][q], Bh[p][q+1]);
                    MMA_BF16(acc[t][n], Ah, Bl[p][q], Bl[p][q+1]);
                    MMA_BF16(acc[t][n], Al, Bh[p][q], Bh[p][q+1]);
                }
            }
        }
    }

    // epilogue
    const int rl = lane >> 2, cl2 = (lane & 3) * 2;
    #pragma unroll
    for (int t = 0; t < 4; t++)
        #pragma unroll
        for (int n = 0; n < 4; n++) {
            const int col = n0 + n0w + n*8 + cl2;
            #pragma unroll
            for (int half = 0; half < 2; half++) {
                const int row = m0 + m0w + t*16 + rl + half*8;
                float ox = (acc[t][n][half*2+0] + bias[col+0]) * scale;
                float oy = (acc[t][n][half*2+1] + bias[col+1]) * scale;
                if (is_qkv) {
                    const int hh = col >> 6, d0 = col & 63;
                    const int bb_ = row >> 10, ss_ = row & 1023;
                    size_t idx = ((size_t)((bb_*HH + hh)*SS + ss_))*DD + d0;
                    uint32_t hi, lo;
                    splitpack(ox, oy, hi, lo);
                    *(uint32_t*)(outHi + idx) = hi;
                    *(uint32_t*)(outLo + idx) = lo;
                } else {
                    float2 o; o.x = ox; o.y = oy;
                    *(float2*)(outp + (size_t)row * EE + col) = o;
                }
            }
        }
}

// ---------------------------------------------------------------------------
// Flash attention on mma.sync bf16 (3-split). CTA = 128 Q rows x (b,h).
// 8 warps, warp = m16 x n64. K/V chunks of 64 rows, double-buffered cp.async.
// Smem: Q stage 32KB | 2 KV stages (Khi,Klo,Vhi,Vlo; 8KB each) | pk[1024].
// launch_bounds(256,2): cap regs at 128 so 2 CTAs/SM co-reside.
// ---------------------------------------------------------------------------
__global__ void __launch_bounds__(256, 2) attn_mma_kernel(
    const int* __restrict__ pos_row, const int* __restrict__ pos_col,
    const float* __restrict__ rel_table)
{
    extern __shared__ char dsm[];
    const uint32_t sbase = smem_u32(dsm);
    const uint32_t sQhi = sbase, sQlo = sbase + 16384u;
    int* pk = (int*)(dsm + 98304);

    const int tid = threadIdx.x;
    const int wid = tid >> 5, lane = tid & 31;
    const int l7 = lane & 7;
    const int rl = lane >> 2, cl2 = (lane & 3) * 2;
    const int achk = lane >> 4;
    const int bchk = (lane >> 3) & 1;

    const int q0 = blockIdx.x * 128;
    const int h = blockIdx.y, b = blockIdx.z;
    const size_t hb = (size_t)(b*HH + h) * SS * DD;

    #pragma unroll
    for (int i = 0; i < 4; i++) {
        int s = tid + i*256;
        pk[s] = (pos_row[b*SS + s] << 5) | pos_col[b*SS + s];
    }

    // Q stage: 128 rows x 64 bf16 hi/lo (group 0)
    {
        const int half = tid >> 7, r = tid & 127;
        const __nv_bfloat16* src = (half ? g_Qlo : g_Qhi) + hb + (size_t)(q0 + r)*DD;
        uint32_t dstrow = (half ? sQlo : sQhi) + (uint32_t)r * 128u;
        #pragma unroll
        for (int ch = 0; ch < 8; ch++)
            CP_ASYNC16(dstrow + ((ch ^ (r & 7)) << 4), src + ch*8);
        CP_COMMIT();
    }

    auto kv_load = [&](int kb, int stg) {
        const int t = tid >> 6, r = tid & 63;
        const __nv_bfloat16* src =
            (t==0 ? g_Khi : t==1 ? g_Klo : t==2 ? g_Vhi : g_Vlo)
            + hb + (size_t)(kb + r)*DD;
        uint32_t dstrow = sbase + 32768u + (uint32_t)stg*32768u
                        + (uint32_t)t*8192u + (uint32_t)r*128u;
        #pragma unroll
        for (int ch = 0; ch < 8; ch++)
            CP_ASYNC16(dstrow + ((ch ^ (r & 7)) << 4), src + ch*8);
        CP_COMMIT();
    };
    kv_load(0, 0);

    CP_WAIT1();
    __syncthreads();

    uint32_t qh[4][4], ql[4][4];
    const uint32_t aq = (uint32_t)(wid*16 + (lane & 15)) * 128u;
    #pragma unroll
    for (int ks = 0; ks < 4; ks++) {
        uint32_t sw = (uint32_t)((2*ks + achk) ^ l7) << 4;
        LDSM4(qh[ks], sQhi + aq + sw);
        LDSM4(ql[ks], sQlo + aq + sw);
    }

    const int rq0 = pk[q0 + wid*16 + rl];
    const int rq1 = pk[q0 + wid*16 + rl + 8];
    const float tb0 = rel_table[0*HH + h];
    const float tb1 = rel_table[1*HH + h];
    const float tb2 = rel_table[2*HH + h];
    const float tb3 = rel_table[3*HH + h];

    float oacc[8][4] = {};
    float m0 = -1e30f, m1 = -1e30f, l0 = 0.f, l1 = 0.f;

    #pragma unroll 1
    for (int kt = 0; kt < SS/64; kt++) {
        CP_WAIT0();
        __syncthreads();
        if (kt + 1 < SS/64) kv_load((kt + 1) * 64, (kt + 1) & 1);

        const uint32_t st  = sbase + 32768u + (uint32_t)(kt & 1) * 32768u;
        const uint32_t Khi = st, Klo = st + 8192u;
        const uint32_t Vhi = st + 16384u, Vlo = st + 24576u;

        // S = Q K^T  (m16 x n64), fp32 accum
        float sacc[8][4] = {};
        #pragma unroll
        for (int ks = 0; ks < 4; ks++) {
            const uint32_t bsw = (uint32_t)((2*ks + bchk) ^ l7) << 4;
            #pragma unroll
            for (int p = 0; p < 4; p++) {
                const uint32_t bo =
                    (uint32_t)(p*16 + l7 + ((lane >> 4) << 3)) * 128u + bsw;
                uint32_t Bh[4], Bl[4];
                LDSM4(Bh, Khi + bo);
                LDSM4(Bl, Klo + bo);
                MMA_BF16(sacc[2*p],   qh[ks], Bh[0], Bh[1]);
                MMA_BF16(sacc[2*p],   qh[ks], Bl[0], Bl[1]);
                MMA_BF16(sacc[2*p],   ql[ks], Bh[0], Bh[1]);
                MMA_BF16(sacc[2*p+1], qh[ks], Bh[2], Bh[3]);
                MMA_BF16(sacc[2*p+1], qh[ks], Bl[2], Bl[3]);
                MMA_BF16(sacc[2*p+1], ql[ks], Bh[2], Bh[3]);
            }
        }

        // bias
        const int kb = kt * 64;
        #pragma unroll
        for (int t = 0; t < 8; t++) {
            int c0 = kb + t*8 + cl2;
            int rk0 = pk[c0], rk1 = pk[c0 + 1];
            int x;
            x = rq0 ^ rk0; sacc[t][0] += (x < 32) ? (((x & 31) == 0) ? tb3 : tb1)
                                                  : (((x & 31) == 0) ? tb2 : tb0);
            x = rq0 ^ rk1; sacc[t][1] += (x < 32) ? (((x & 31) == 0) ? tb3 : tb1)
                                                  : (((x & 31) == 0) ? tb2 : tb0);
            x = rq1 ^ rk0; sacc[t][2] += (x < 32) ? (((x & 31) == 0) ? tb3 : tb1)
                                                  : (((x & 31) == 0) ? tb2 : tb0);
            x = rq1 ^ rk1; sacc[t][3] += (x < 32) ? (((x & 31) == 0) ? tb3 : tb1)
                                                  : (((x & 31) == 0) ? tb2 : tb0);
        }

        // online softmax (MUFU exp; 4 lanes/row)
        float mx0 = sacc[0][0], mx1 = sacc[0][2];
        #pragma unroll
        for (int t = 0; t < 8; t++) {
            mx0 = fmaxf(mx0, fmaxf(sacc[t][0], sacc[t][1]));
            mx1 = fmaxf(mx1, fmaxf(sacc[t][2], sacc[t][3]));
        }
        mx0 = fmaxf(mx0, __shfl_xor_sync(0xffffffffu, mx0, 1));
        mx0 = fmaxf(mx0, __shfl_xor_sync(0xffffffffu, mx0, 2));
        mx1 = fmaxf(mx1, __shfl_xor_sync(0xffffffffu, mx1, 1));
        mx1 = fmaxf(mx1, __shfl_xor_sync(0xffffffffu, mx1, 2));
        float mn0 = fmaxf(m0, mx0), mn1 = fmaxf(m1, mx1);
        float sc0 = __expf(m0 - mn0), sc1 = __expf(m1 - mn1);
        m0 = mn0; m1 = mn1;
        float rs0 = 0.f, rs1 = 0.f;
        #pragma unroll
        for (int t = 0; t < 8; t++) {
            sacc[t][0] = __expf(sacc[t][0] - mn0);
            sacc[t][1] = __expf(sacc[t][1] - mn0);
            sacc[t][2] = __expf(sacc[t][2] - mn1);
            sacc[t][3] = __expf(sacc[t][3] - mn1);
            rs0 += sacc[t][0] + sacc[t][1];
            rs1 += sacc[t][2] + sacc[t][3];
        }
        rs0 += __shfl_xor_sync(0xffffffffu, rs0, 1);
        rs0 += __shfl_xor_sync(0xffffffffu, rs0, 2);
        rs1 += __shfl_xor_sync(0xffffffffu, rs1, 1);
        rs1 += __shfl_xor_sync(0xffffffffu, rs1, 2);
        l0 = l0 * sc0 + rs0;
        l1 = l1 * sc1 + rs1;
        #pragma unroll
        for (int t = 0; t < 8; t++) {
            oacc[t][0] *= sc0; oacc[t][1] *= sc0;
            oacc[t][2] *= sc1; oacc[t][3] *= sc1;
        }

        // O += P V : P fragments straight from sacc (hi/lo split)
        #pragma unroll
        for (int ks = 0; ks < 4; ks++) {
            uint32_t ph[4], pl[4];
            splitpack(sacc[2*ks][0],   sacc[2*ks][1],   ph[0], pl[0]);
            splitpack(sacc[2*ks][2],   sacc[2*ks][3],   ph[1], pl[1]);
            splitpack(sacc[2*ks+1][0], sacc[2*ks+1][1], ph[2], pl[2]);
            splitpack(sacc[2*ks+1][2], sacc[2*ks+1][3], ph[3], pl[3]);
            const uint32_t vr =
                (uint32_t)(ks*16 + l7 + (((lane >> 3) & 1) << 3)) * 128u;
            #pragma unroll
            for (int p = 0; p < 4; p++) {
                const uint32_t vsw = (uint32_t)((2*p + achk) ^ l7) << 4;
                uint32_t Vh[4], Vl[4];
                LDSM4T(Vh, Vhi + vr + vsw);
                LDSM4T(Vl, Vlo + vr + vsw);
                MMA_BF16(oacc[2*p],   ph, Vh[0], Vh[1]);
                MMA_BF16(oacc[2*p],   ph, Vl[0], Vl[1]);
                MMA_BF16(oacc[2*p],   pl, Vh[0], Vh[1]);
                MMA_BF16(oacc[2*p+1], ph, Vh[2], Vh[3]);
                MMA_BF16(oacc[2*p+1], ph, Vl[2], Vl[3]);
                MMA_BF16(oacc[2*p+1], pl, Vh[2], Vh[3]);
            }
        }
    }

    // epilogue: normalize, emit bf16 hi/lo AO at [B,S,E] (e = h*64+d)
    const float inv0 = 1.0f / l0, inv1 = 1.0f / l1;
    const int qrow0 = q0 + wid*16 + rl;
    #pragma unroll
    for (int t = 0; t < 8; t++) {
        const int e = h*64 + t*8 + cl2;
        size_t i0 = (size_t)(b*SS + qrow0) * EE + e;
        size_t i1 = (size_t)(b*SS + qrow0 + 8) * EE + e;
        uint32_t hi, lo;
        splitpack(oacc[t][0] * inv0, oacc[t][1] * inv0, hi, lo);
        *(uint32_t*)(g_AOhi + i0) = hi;
        *(uint32_t*)(g_AOlo + i0) = lo;
        splitpack(oacc[t][2] * inv1, oacc[t][3] * inv1, hi, lo);
        *(uint32_t*)(g_AOhi + i1) = hi;
        *(uint32_t*)(g_AOlo + i1) = lo;
    }
}

// ---------------------------------------------------------------------------
extern "C" void kernel_launch(void* const* d_in, const int* in_sizes, int n_in,
                              void* d_out, int out_size) {
    const float* X  = (const float*)d_in[0];
    const int*   pr = (const int*)  d_in[1];
    const int*   pc = (const int*)  d_in[2];
    const float* qw = (const float*)d_in[3];
    const float* qb = (const float*)d_in[4];
    const float* kw = (const float*)d_in[5];
    const float* kb = (const float*)d_in[6];
    const float* vw = (const float*)d_in[7];
    const float* vb = (const float*)d_in[8];
    const float* ow = (const float*)d_in[9];
    const float* ob = (const float*)d_in[10];
    const float* rt = (const float*)d_in[11];
    float* out = (float*)d_out;

    const int DSMEM_G = 3 * 32768;                 // 3-stage pipeline
    cudaFuncSetAttribute(gemm_mma_kernel,
                         cudaFuncAttributeMaxDynamicSharedMemorySize, DSMEM_G);
    const int DSMEM_A = 32768 + 2*32768 + 4096;    // 102400
    cudaFuncSetAttribute(attn_mma_kernel,
                         cudaFuncAttributeMaxDynamicSharedMemorySize, DSMEM_A);

    split_all_kernel<<<3072 + 4*576, 256>>>(X, qw, kw, vw, ow);

    dim3 g1(EE/128, MT/128, 3);
    gemm_mma_kernel<<<g1, 256, DSMEM_G>>>(qb, kb, vb, nullptr, 0, 1);

    dim3 g2(SS/128, HH, BB);
    attn_mma_kernel<<<g2, 256, DSMEM_A>>>(pr, pc, rt);

    dim3 g3(EE/128, MT/128, 1);
    gemm_mma_kernel<<<g3, 256, DSMEM_G>>>(ob, ob, ob, out, 3, 0);
}